// round 7
// baseline (speedup 1.0000x reference)
#include <cuda_runtime.h>
#include <cuda_bf16.h>

#define NN 100000
#define EE 800000
#define HH 128
#define BB 64
#define NB1 196   // ceil(NN/512)
#define MMJ 64    // nodes per k_gmm block

typedef unsigned long long u64;

__device__ __forceinline__ u64 ffma2(u64 a, u64 b, u64 c) {
    u64 d;
    asm("fma.rn.f32x2 %0, %1, %2, %3;" : "=l"(d) : "l"(a), "l"(b), "l"(c));
    return d;
}
__device__ __forceinline__ u64 dupf(float x) {
    u64 d;
    asm("mov.b64 %0, {%1, %1};" : "=l"(d) : "f"(x));
    return d;
}

// ---------------- scratch (device globals: no runtime allocation) ----------------
__device__ float g_u[(size_t)NN * HH];            // hop-2 node features (fp32, head path)
__device__ __nv_bfloat162 g_ub[(size_t)NN * 64];  // bf16 u, buffer A (hop0 out, hop1 in)
__device__ __nv_bfloat162 g_ub2[(size_t)NN * 64]; // bf16 u, buffer B (hop1 out, hop2 in)
__device__ int   g_deg[NN];
__device__ int   g_start[NN + 1];
__device__ int   g_cursor[NN];
__device__ int   g_bsum[NB1 + 4];
__device__ int   g_ccol[EE];
__device__ float g_cea[EE];
__device__ float g_gs0[BB * HH], g_gs1[BB * HH];
__device__ float g_cnt[2 * BB];
__device__ float g_v0t[BB * HH], g_v1t[BB * HH];
__device__ float g_scal[BB * 10];                 // s0,s1,p0,p1,a0,a1,d00,d01,d10,d11
__device__ float g_spvec[HH], g_actop[HH], g_acbot[HH];
__device__ float g_c0;

// ---------------- zero + folded final-layer vectors (merged) ----------------
__global__ void k_zero(const float* __restrict__ spw, const float* __restrict__ spb,
                       const float* __restrict__ acw, const float* __restrict__ acb,
                       const float* __restrict__ lastw, const float* __restrict__ lastb) {
    int i = blockIdx.x * blockDim.x + threadIdx.x;
    if (i < NN) g_deg[i] = 0;
    if (i < BB * HH) { g_gs0[i] = 0.f; g_gs1[i] = 0.f; }
    if (i < 2 * BB) { g_cnt[i] = 0.f; }
    if (i == 0) g_start[NN] = EE;
    if (blockIdx.x == 0) {
        int t = threadIdx.x;  // 256
        if (t < HH) {
            float s = 0.f;
            for (int j = 0; j < HH; j++) s += spw[t * HH + j] * lastw[j];
            g_spvec[t] = s;
        }
        {
            float s = 0.f;
            for (int j = 0; j < HH; j++) s += acw[t * HH + j] * lastw[HH + j];
            if (t < HH) g_actop[t] = s; else g_acbot[t - HH] = s;
        }
        if (t < 32) {
            float s = 0.f;
            for (int j = t; j < HH; j += 32) s += spb[j] * lastw[j] + acb[j] * lastw[HH + j];
            for (int o = 16; o; o >>= 1) s += __shfl_down_sync(0xffffffffu, s, o);
            if (t == 0) g_c0 = s + lastb[0];
        }
    }
}

__global__ void k_hist(const int* __restrict__ row) {
    int e = blockIdx.x * blockDim.x + threadIdx.x;
    if (e < EE) atomicAdd(&g_deg[row[e]], 1);
}

// ---- scan: block sums, then per-block (local boff reduction + intra-block scan) ----
__global__ void k_scan1() {
    int t = threadIdx.x;                     // 256 threads, 512 nodes/block
    int n0 = blockIdx.x * 512;
    int s = 0;
    int i = n0 + t;
    if (i < NN) s += g_deg[i];
    if (i + 256 < n0 + 512 && i + 256 < NN) s += g_deg[i + 256];
    int lane = t & 31, warp = t >> 5;
    for (int o = 16; o; o >>= 1) s += __shfl_down_sync(0xffffffffu, s, o);
    __shared__ int ws[8];
    if (lane == 0) ws[warp] = s;
    __syncthreads();
    if (t == 0) {
        int tot = 0;
        #pragma unroll
        for (int w = 0; w < 8; w++) tot += ws[w];
        g_bsum[blockIdx.x] = tot;
    }
}

__global__ void k_scan3() {
    int t = threadIdx.x, blk = blockIdx.x;   // 256 threads
    __shared__ int ws[8], wo[8], sBoff;
    int lane = t & 31, warp = t >> 5;

    // block offset = sum of bsum[0..blk-1] (NB1 = 196 <= 256)
    int bv = (t < blk) ? g_bsum[t] : 0;
    for (int o = 16; o; o >>= 1) bv += __shfl_down_sync(0xffffffffu, bv, o);
    if (lane == 0) ws[warp] = bv;
    __syncthreads();
    if (t == 0) {
        int tot = 0;
        #pragma unroll
        for (int w = 0; w < 8; w++) tot += ws[w];
        sBoff = tot;
    }
    __syncthreads();

    // intra-block exclusive scan of 512 degrees (2 per thread)
    int i0 = blk * 512 + t * 2;
    int d0 = (i0 < NN) ? g_deg[i0] : 0;
    int d1 = (i0 + 1 < NN) ? g_deg[i0 + 1] : 0;
    int s = d0 + d1;
    int v = s;
    for (int o = 1; o < 32; o <<= 1) {
        int u = __shfl_up_sync(0xffffffffu, v, o);
        if (lane >= o) v += u;
    }
    if (lane == 31) ws[warp] = v;
    __syncthreads();
    if (t == 0) {
        int run = 0;
        #pragma unroll
        for (int w = 0; w < 8; w++) { wo[w] = run; run += ws[w]; }
    }
    __syncthreads();
    int ex = v - s + wo[warp] + sBoff;
    if (i0 < NN)     { g_start[i0] = ex;          g_cursor[i0] = ex; }
    if (i0 + 1 < NN) { g_start[i0 + 1] = ex + d0; g_cursor[i0 + 1] = ex + d0; }
}

__global__ void k_fill(const int* __restrict__ row, const int* __restrict__ col,
                       const float* __restrict__ ea) {
    int e = blockIdx.x * blockDim.x + threadIdx.x;
    if (e >= EE) return;
    int r = row[e];
    int idx = atomicAdd(&g_cursor[r], 1);
    g_ccol[idx] = col[e];
    g_cea[idx]  = ea[e];
}

// hop 0 fused (u==0): warp per node; lanes split edges for third term; emit bf16 u -> buf A.
__global__ void k_hop0(const float* __restrict__ x,
                       const float* __restrict__ l3w, const float* __restrict__ l3b,
                       const float* __restrict__ l0w, const float* __restrict__ l0b,
                       const float* __restrict__ l1b,
                       const float* __restrict__ l2w, const float* __restrict__ l2b) {
    int warp = threadIdx.x >> 5, lane = threadIdx.x & 31;
    int n = blockIdx.x * 8 + warp;
    if (n >= NN) return;
    float w = l3w[0], b = l3b[0];
    int s = g_start[n], e = g_start[n + 1];
    float acc = 0.f;
    for (int t = s + lane; t < e; t += 32) acc += fmaxf(g_cea[t] * w + b, 0.f);
    for (int o = 16; o; o >>= 1) acc += __shfl_xor_sync(0xffffffffu, acc, o);
    float third = (e > s) ? acc / (float)(e - s) : 0.f;
    float xv = x[n];
    int h0 = lane * 4;
    float v0 = xv * l0w[h0]     + third * l2w[h0]     + l0b[h0]     + l1b[h0]     + l2b[h0];
    float v1 = xv * l0w[h0 + 1] + third * l2w[h0 + 1] + l0b[h0 + 1] + l1b[h0 + 1] + l2b[h0 + 1];
    float v2 = xv * l0w[h0 + 2] + third * l2w[h0 + 2] + l0b[h0 + 2] + l1b[h0 + 2] + l2b[h0 + 2];
    float v3 = xv * l0w[h0 + 3] + third * l2w[h0 + 3] + l0b[h0 + 3] + l1b[h0 + 3] + l2b[h0 + 3];
    __nv_bfloat162 lo = __floats2bfloat162_rn(fmaxf(v0, 0.f), fmaxf(v1, 0.f));
    __nv_bfloat162 hi = __floats2bfloat162_rn(fmaxf(v2, 0.f), fmaxf(v3, 0.f));
    uint2 pk;
    pk.x = *reinterpret_cast<unsigned*>(&lo);
    pk.y = *reinterpret_cast<unsigned*>(&hi);
    reinterpret_cast<uint2*>(g_ub)[(size_t)n * 32 + lane] = pk;
}

// fused gather + matmul + hop update, DOUBLE-BUFFERED bf16 node features.
// hop==1: read buf A (g_ub),  write buf B (g_ub2)  [no same-buffer RAW race]
// hop==2: read buf B (g_ub2), write fp32 g_u
__global__ __launch_bounds__(256) void k_gmm(
    const float* __restrict__ x, const float* __restrict__ W1,
    const float* __restrict__ l3w, const float* __restrict__ l3b,
    const float* __restrict__ l0w, const float* __restrict__ l2w,
    const float* __restrict__ b0, const float* __restrict__ b1,
    const float* __restrict__ b2, int hop) {
    extern __shared__ float sm[];
    float* sW = sm;                      // [128][128] row = k
    float* sA = sm + HH * HH;            // [64][128]  node-major
    float* sT = sm + HH * HH + MMJ * HH; // [64] third terms
    int tid = threadIdx.x;
    int lane = tid & 31, warp = tid >> 5;

    const float4* W4 = reinterpret_cast<const float4*>(W1);
    float4* sW4 = reinterpret_cast<float4*>(sW);
    #pragma unroll
    for (int i = tid; i < HH * HH / 4; i += 256) sW4[i] = W4[i];

    int n0 = blockIdx.x * MMJ;
    const uint2* ub = reinterpret_cast<const uint2*>(hop == 1 ? g_ub : g_ub2);
    float wl3 = l3w[0], bl3 = l3b[0];

    // ---- gather phase ----
    #pragma unroll 1
    for (int r = 0; r < 8; r++) {
        int j = warp * 8 + r;
        int n = n0 + j;
        float ax = 0.f, ay = 0.f, az = 0.f, aw = 0.f, tacc = 0.f;
        float inv = 0.f;
        if (n < NN) {
            int s = g_start[n], e = g_start[n + 1];
            int t = s;
            for (; t + 3 < e; t += 4) {
                int c0 = g_ccol[t], c1 = g_ccol[t + 1], c2 = g_ccol[t + 2], c3 = g_ccol[t + 3];
                float a0 = g_cea[t], a1 = g_cea[t + 1], a2 = g_cea[t + 2], a3 = g_cea[t + 3];
                uint2 r0 = ub[(size_t)c0 * 32 + lane];
                uint2 r1 = ub[(size_t)c1 * 32 + lane];
                uint2 r2 = ub[(size_t)c2 * 32 + lane];
                uint2 r3 = ub[(size_t)c3 * 32 + lane];
                float2 p0 = __bfloat1622float2(*reinterpret_cast<__nv_bfloat162*>(&r0.x));
                float2 q0 = __bfloat1622float2(*reinterpret_cast<__nv_bfloat162*>(&r0.y));
                float2 p1 = __bfloat1622float2(*reinterpret_cast<__nv_bfloat162*>(&r1.x));
                float2 q1 = __bfloat1622float2(*reinterpret_cast<__nv_bfloat162*>(&r1.y));
                float2 p2 = __bfloat1622float2(*reinterpret_cast<__nv_bfloat162*>(&r2.x));
                float2 q2 = __bfloat1622float2(*reinterpret_cast<__nv_bfloat162*>(&r2.y));
                float2 p3 = __bfloat1622float2(*reinterpret_cast<__nv_bfloat162*>(&r3.x));
                float2 q3 = __bfloat1622float2(*reinterpret_cast<__nv_bfloat162*>(&r3.y));
                ax += a0 * p0.x + a1 * p1.x + a2 * p2.x + a3 * p3.x;
                ay += a0 * p0.y + a1 * p1.y + a2 * p2.y + a3 * p3.y;
                az += a0 * q0.x + a1 * q1.x + a2 * q2.x + a3 * q3.x;
                aw += a0 * q0.y + a1 * q1.y + a2 * q2.y + a3 * q3.y;
                tacc += fmaxf(a0 * wl3 + bl3, 0.f) + fmaxf(a1 * wl3 + bl3, 0.f)
                      + fmaxf(a2 * wl3 + bl3, 0.f) + fmaxf(a3 * wl3 + bl3, 0.f);
            }
            for (; t < e; t++) {
                int c0 = g_ccol[t];
                float a0 = g_cea[t];
                uint2 r0 = ub[(size_t)c0 * 32 + lane];
                float2 p0 = __bfloat1622float2(*reinterpret_cast<__nv_bfloat162*>(&r0.x));
                float2 q0 = __bfloat1622float2(*reinterpret_cast<__nv_bfloat162*>(&r0.y));
                ax += a0 * p0.x; ay += a0 * p0.y; az += a0 * q0.x; aw += a0 * q0.y;
                tacc += fmaxf(a0 * wl3 + bl3, 0.f);
            }
            inv = (e > s) ? 1.f / (float)(e - s) : 0.f;
        }
        *reinterpret_cast<float4*>(&sA[j * HH + lane * 4]) =
            make_float4(ax * inv, ay * inv, az * inv, aw * inv);
        if (lane == 0) sT[j] = tacc * inv;
    }
    __syncthreads();

    // ---- matmul phase ----
    int c0 = lane * 4, j0 = warp * 8;
    u64 acc[8][2];
    #pragma unroll
    for (int r = 0; r < 8; r++) { acc[r][0] = 0ULL; acc[r][1] = 0ULL; }

    #pragma unroll 2
    for (int k = 0; k < HH; k += 4) {
        float4 a[8];
        #pragma unroll
        for (int r = 0; r < 8; r++)
            a[r] = *reinterpret_cast<const float4*>(&sA[(j0 + r) * HH + k]);  // broadcast
        #pragma unroll
        for (int kk = 0; kk < 4; kk++) {
            const u64* wrow = reinterpret_cast<const u64*>(&sW[(k + kk) * HH + c0]);
            u64 w0 = wrow[0], w1 = wrow[1];
            #pragma unroll
            for (int r = 0; r < 8; r++) {
                u64 ad = dupf(reinterpret_cast<const float*>(&a[r])[kk]);
                acc[r][0] = ffma2(ad, w0, acc[r][0]);
                acc[r][1] = ffma2(ad, w1, acc[r][1]);
            }
        }
    }

    float4 w0v = *reinterpret_cast<const float4*>(&l0w[c0]);
    float4 w2v = *reinterpret_cast<const float4*>(&l2w[c0]);
    float4 p0 = *reinterpret_cast<const float4*>(&b0[c0]);
    float4 p1 = *reinterpret_cast<const float4*>(&b1[c0]);
    float4 p2 = *reinterpret_cast<const float4*>(&b2[c0]);
    float bias0 = p0.x + p1.x + p2.x, bias1 = p0.y + p1.y + p2.y;
    float bias2 = p0.z + p1.z + p2.z, bias3 = p0.w + p1.w + p2.w;

    uint2* ubw = reinterpret_cast<uint2*>(g_ub2);  // hop 1 writes buf B
    #pragma unroll
    for (int r = 0; r < 8; r++) {
        int n = n0 + j0 + r;
        if (n < NN) {
            float xv = x[n], tv = sT[j0 + r];
            float2 f0 = *reinterpret_cast<float2*>(&acc[r][0]);
            float2 f1 = *reinterpret_cast<float2*>(&acc[r][1]);
            float4 o;
            o.x = fmaxf(xv * w0v.x + tv * w2v.x + bias0 + f0.x, 0.f);
            o.y = fmaxf(xv * w0v.y + tv * w2v.y + bias1 + f0.y, 0.f);
            o.z = fmaxf(xv * w0v.z + tv * w2v.z + bias2 + f1.x, 0.f);
            o.w = fmaxf(xv * w0v.w + tv * w2v.w + bias3 + f1.y, 0.f);
            if (hop == 1) {
                __nv_bfloat162 lo = __floats2bfloat162_rn(o.x, o.y);
                __nv_bfloat162 hi = __floats2bfloat162_rn(o.z, o.w);
                uint2 pk;
                pk.x = *reinterpret_cast<unsigned*>(&lo);
                pk.y = *reinterpret_cast<unsigned*>(&hi);
                ubw[(size_t)n * 32 + lane] = pk;
            } else {
                *reinterpret_cast<float4*>(&g_u[(size_t)n * HH + c0]) = o;
            }
        }
    }
}

// per-graph pooled sums (batch sorted -> register accumulate, flush on change)
__global__ void k_pool(const float* __restrict__ x, const int* __restrict__ batch) {
    int h = threadIdx.x;               // 128
    int n0 = blockIdx.x * 128;
    if (n0 >= NN) return;
    int n1 = n0 + 128; if (n1 > NN) n1 = NN;
    int gcur = batch[n0];
    float a0 = 0.f, a1 = 0.f, c0 = 0.f, c1 = 0.f;
    for (int n = n0; n < n1; n++) {
        int g = batch[n];
        if (g != gcur) {
            atomicAdd(&g_gs0[gcur * HH + h], a0);
            atomicAdd(&g_gs1[gcur * HH + h], a1);
            if (h == 0) { atomicAdd(&g_cnt[gcur], c0); atomicAdd(&g_cnt[BB + gcur], c1); }
            a0 = a1 = c0 = c1 = 0.f;
            gcur = g;
        }
        float xv = x[n];
        float uv = g_u[(size_t)n * HH + h];
        a0 += uv * (1.f - xv); a1 += uv * xv;
        c0 += 1.f - xv;        c1 += xv;
    }
    atomicAdd(&g_gs0[gcur * HH + h], a0);
    atomicAdd(&g_gs1[gcur * HH + h], a1);
    if (h == 0) { atomicAdd(&g_cnt[gcur], c0); atomicAdd(&g_cnt[BB + gcur], c1); }
}

// per-graph: hc0/hc1, folded attention vectors v0/v1 = att_w @ hc, and 10 scalars
__global__ void k_graph(const float* __restrict__ attw, const float* __restrict__ attb) {
    __shared__ float hc0[HH], hc1[HH], v0[2 * HH], v1[2 * HH];
    int g = blockIdx.x, t = threadIdx.x;  // 256 threads
    if (t < HH) {
        float c0 = g_cnt[g], c1 = g_cnt[BB + g];
        hc0[t] = (c0 > 0.f) ? g_gs0[g * HH + t] / c0 : 0.f;
        hc1[t] = (c1 > 0.f) ? g_gs1[g * HH + t] / c1 : 0.f;
    }
    __syncthreads();
    {
        float s0 = 0.f, s1 = 0.f;
        const float* wrow = attw + t * HH;
        for (int j = 0; j < HH; j++) { float w = wrow[j]; s0 += w * hc0[j]; s1 += w * hc1[j]; }
        v0[t] = s0; v1[t] = s1;
        if (t < HH) { g_v0t[g * HH + t] = s0; g_v1t[g * HH + t] = s1; }
    }
    __syncthreads();
    int warp = t >> 5, lane = t & 31;
    for (int id = warp; id < 10; id += 8) {
        const float* vec; const float* hc;
        switch (id) {
            case 0: vec = attb;     hc = hc0; break;  // s0
            case 1: vec = attb;     hc = hc1; break;  // s1
            case 2: vec = g_spvec;  hc = hc0; break;  // p0
            case 3: vec = g_spvec;  hc = hc1; break;  // p1
            case 4: vec = g_acbot;  hc = hc0; break;  // a0
            case 5: vec = g_acbot;  hc = hc1; break;  // a1
            case 6: vec = v0 + HH;  hc = hc0; break;  // d00
            case 7: vec = v0 + HH;  hc = hc1; break;  // d01
            case 8: vec = v1 + HH;  hc = hc0; break;  // d10
            default: vec = v1 + HH; hc = hc1; break;  // d11
        }
        float s = 0.f;
        for (int j = lane; j < HH; j += 32) s += vec[j] * hc[j];
        for (int o = 16; o; o >>= 1) s += __shfl_down_sync(0xffffffffu, s, o);
        if (lane == 0) g_scal[g * 10 + id] = s;
    }
}

// per-node head: 3 dots of length 128 + softmax over 2 + folded output
__global__ void k_final(const float* __restrict__ x, const int* __restrict__ batch,
                        float* __restrict__ out) {
    int warp = threadIdx.x >> 5, lane = threadIdx.x & 31;
    int n = blockIdx.x * 8 + warp;
    if (n >= NN) return;
    int g = batch[n];
    float4 uv = *reinterpret_cast<const float4*>(&g_u[(size_t)n * HH + lane * 4]);
    float4 vA = *reinterpret_cast<const float4*>(&g_v0t[g * HH + lane * 4]);
    float4 vB = *reinterpret_cast<const float4*>(&g_v1t[g * HH + lane * 4]);
    float4 vC = *reinterpret_cast<const float4*>(&g_actop[lane * 4]);
    float da = uv.x * vA.x + uv.y * vA.y + uv.z * vA.z + uv.w * vA.w;
    float db = uv.x * vB.x + uv.y * vB.y + uv.z * vB.z + uv.w * vB.w;
    float dc = uv.x * vC.x + uv.y * vC.y + uv.z * vC.z + uv.w * vC.w;
    for (int o = 16; o; o >>= 1) {
        da += __shfl_down_sync(0xffffffffu, da, o);
        db += __shfl_down_sync(0xffffffffu, db, o);
        dc += __shfl_down_sync(0xffffffffu, dc, o);
    }
    if (lane == 0) {
        const float* sc = &g_scal[g * 10];
        bool xb = x[n] > 0.5f;
        float w0 = da + (xb ? sc[6] : sc[7]) + sc[0];
        float w1 = db + (xb ? sc[8] : sc[9]) + sc[1];
        float m = fmaxf(w0, w1);
        float e0 = __expf(w0 - m), e1 = __expf(w1 - m);
        float sw = e0 / (e0 + e1);
        out[n] = sw * sc[2] + (1.f - sw) * sc[3] + dc + (xb ? sc[4] : sc[5]) + g_c0;
    }
}

// ---------------- launch ----------------
extern "C" void kernel_launch(void* const* d_in, const int* in_sizes, int n_in,
                              void* d_out, int out_size) {
    int base = (n_in >= 21) ? 5 : 4;
    const float* x     = (const float*)d_in[0];
    const int*   ei    = (const int*)d_in[1];
    const float* ea    = (const float*)d_in[2];
    const int*   batch = (const int*)d_in[3];
    const float* l0w   = (const float*)d_in[base + 0];
    const float* l0b   = (const float*)d_in[base + 1];
    const float* l1w   = (const float*)d_in[base + 2];
    const float* l1b   = (const float*)d_in[base + 3];
    const float* l2w   = (const float*)d_in[base + 4];
    const float* l2b   = (const float*)d_in[base + 5];
    const float* l3w   = (const float*)d_in[base + 6];
    const float* l3b   = (const float*)d_in[base + 7];
    const float* attw  = (const float*)d_in[base + 8];
    const float* attb  = (const float*)d_in[base + 9];
    const float* spw   = (const float*)d_in[base + 10];
    const float* spb   = (const float*)d_in[base + 11];
    const float* acw   = (const float*)d_in[base + 12];
    const float* acb   = (const float*)d_in[base + 13];
    const float* lastw = (const float*)d_in[base + 14];
    const float* lastb = (const float*)d_in[base + 15];
    const int* row = ei;
    const int* col = ei + EE;
    float* out = (float*)d_out;

    const int SMEM_GMM = (HH * HH + MMJ * HH + MMJ) * (int)sizeof(float);  // 98560 B
    cudaFuncSetAttribute(k_gmm, cudaFuncAttributeMaxDynamicSharedMemorySize, SMEM_GMM);

    k_zero<<<(NN + 255) / 256, 256>>>(spw, spb, acw, acb, lastw, lastb);
    k_hist<<<(EE + 255) / 256, 256>>>(row);
    k_scan1<<<NB1, 256>>>();
    k_scan3<<<NB1, 256>>>();
    k_fill<<<(EE + 255) / 256, 256>>>(row, col, ea);

    // hop 0 (u == 0): fused third+update, bf16 out -> buf A
    k_hop0<<<(NN + 7) / 8, 256>>>(x, l3w, l3b, l0w, l0b, l1b, l2w, l2b);

    // hop 1 (A -> B, bf16), hop 2 (B -> fp32 g_u): fused gather+matmul
    for (int i = 1; i < 3; i++) {
        k_gmm<<<(NN + MMJ - 1) / MMJ, 256, SMEM_GMM>>>(
            x, l1w + i * HH * HH, l3w + i, l3b + i,
            l0w + i * HH, l2w + i * HH,
            l0b + i * HH, l1b + i * HH, l2b + i * HH, i);
    }

    k_pool<<<(NN + 127) / 128, 128>>>(x, batch);
    k_graph<<<BB, 256>>>(attw, attb);
    k_final<<<NN / 8, 256>>>(x, batch, out);
}

// round 8
// speedup vs baseline: 1.0846x; 1.0846x over previous
#include <cuda_runtime.h>
#include <cuda_bf16.h>

#define NN 100000
#define EE 800000
#define HH 128
#define BB 64
#define NB1 196   // ceil(NN/512)
#define MMJ 64    // nodes per k_mm block
#define AST 68    // sAT row stride (floats)

typedef unsigned long long u64;

__device__ __forceinline__ u64 ffma2(u64 a, u64 b, u64 c) {
    u64 d;
    asm("fma.rn.f32x2 %0, %1, %2, %3;" : "=l"(d) : "l"(a), "l"(b), "l"(c));
    return d;
}
__device__ __forceinline__ u64 dupf(float x) {
    u64 d;
    asm("mov.b64 %0, {%1, %1};" : "=l"(d) : "f"(x));
    return d;
}

// ---------------- scratch (device globals: no runtime allocation) ----------------
__device__ float g_u[(size_t)NN * HH];           // hop-2 node features (fp32, head path)
__device__ __nv_bfloat162 g_ub[(size_t)NN * 64]; // bf16 u (gather input)
__device__ float g_mean[(size_t)NN * HH];        // seg_mean(ea*u[col]) per node
__device__ float g_third[NN];                    // seg_mean(ee) per node (per hop)
__device__ int   g_deg[NN];
__device__ int   g_start[NN + 1];
__device__ int   g_cursor[NN];
__device__ int   g_bsum[NB1 + 4];
__device__ int   g_ccol[EE];
__device__ float g_cea[EE];
__device__ float g_gs0[BB * HH], g_gs1[BB * HH];
__device__ float g_cnt[2 * BB];
__device__ float g_v0t[BB * HH], g_v1t[BB * HH];
__device__ float g_scal[BB * 10];                // s0,s1,p0,p1,a0,a1,d00,d01,d10,d11
__device__ float g_spvec[HH], g_actop[HH], g_acbot[HH];
__device__ float g_c0;

// ---------------- zero + folded final-layer vectors (merged) ----------------
__global__ void k_zero(const float* __restrict__ spw, const float* __restrict__ spb,
                       const float* __restrict__ acw, const float* __restrict__ acb,
                       const float* __restrict__ lastw, const float* __restrict__ lastb) {
    int i = blockIdx.x * blockDim.x + threadIdx.x;
    if (i < NN) g_deg[i] = 0;
    if (i < BB * HH) { g_gs0[i] = 0.f; g_gs1[i] = 0.f; }
    if (i < 2 * BB) { g_cnt[i] = 0.f; }
    if (i == 0) g_start[NN] = EE;
    if (blockIdx.x == 0) {
        int t = threadIdx.x;  // 256
        if (t < HH) {
            float s = 0.f;
            for (int j = 0; j < HH; j++) s += spw[t * HH + j] * lastw[j];
            g_spvec[t] = s;
        }
        {
            float s = 0.f;
            for (int j = 0; j < HH; j++) s += acw[t * HH + j] * lastw[HH + j];
            if (t < HH) g_actop[t] = s; else g_acbot[t - HH] = s;
        }
        if (t < 32) {
            float s = 0.f;
            for (int j = t; j < HH; j += 32) s += spb[j] * lastw[j] + acb[j] * lastw[HH + j];
            for (int o = 16; o; o >>= 1) s += __shfl_down_sync(0xffffffffu, s, o);
            if (t == 0) g_c0 = s + lastb[0];
        }
    }
}

__global__ void k_hist(const int* __restrict__ row) {
    int e = blockIdx.x * blockDim.x + threadIdx.x;
    if (e < EE) atomicAdd(&g_deg[row[e]], 1);
}

// ---- scan: block sums, then per-block (local boff reduction + intra-block scan) ----
__global__ void k_scan1() {
    int t = threadIdx.x;                     // 256 threads, 512 nodes/block
    int n0 = blockIdx.x * 512;
    int s = 0;
    int i = n0 + t;
    if (i < NN) s += g_deg[i];
    if (i + 256 < n0 + 512 && i + 256 < NN) s += g_deg[i + 256];
    int lane = t & 31, warp = t >> 5;
    for (int o = 16; o; o >>= 1) s += __shfl_down_sync(0xffffffffu, s, o);
    __shared__ int ws[8];
    if (lane == 0) ws[warp] = s;
    __syncthreads();
    if (t == 0) {
        int tot = 0;
        #pragma unroll
        for (int w = 0; w < 8; w++) tot += ws[w];
        g_bsum[blockIdx.x] = tot;
    }
}

__global__ void k_scan3() {
    int t = threadIdx.x, blk = blockIdx.x;   // 256 threads
    __shared__ int ws[8], wo[8], sBoff;
    int lane = t & 31, warp = t >> 5;

    // block offset = sum of bsum[0..blk-1] (NB1 = 196 <= 256)
    int bv = (t < blk) ? g_bsum[t] : 0;
    for (int o = 16; o; o >>= 1) bv += __shfl_down_sync(0xffffffffu, bv, o);
    if (lane == 0) ws[warp] = bv;
    __syncthreads();
    if (t == 0) {
        int tot = 0;
        #pragma unroll
        for (int w = 0; w < 8; w++) tot += ws[w];
        sBoff = tot;
    }
    __syncthreads();

    // intra-block exclusive scan of 512 degrees (2 per thread)
    int i0 = blk * 512 + t * 2;
    int d0 = (i0 < NN) ? g_deg[i0] : 0;
    int d1 = (i0 + 1 < NN) ? g_deg[i0 + 1] : 0;
    int s = d0 + d1;
    int v = s;
    for (int o = 1; o < 32; o <<= 1) {
        int u = __shfl_up_sync(0xffffffffu, v, o);
        if (lane >= o) v += u;
    }
    if (lane == 31) ws[warp] = v;
    __syncthreads();
    if (t == 0) {
        int run = 0;
        #pragma unroll
        for (int w = 0; w < 8; w++) { wo[w] = run; run += ws[w]; }
    }
    __syncthreads();
    int ex = v - s + wo[warp] + sBoff;
    if (i0 < NN)     { g_start[i0] = ex;          g_cursor[i0] = ex; }
    if (i0 + 1 < NN) { g_start[i0 + 1] = ex + d0; g_cursor[i0 + 1] = ex + d0; }
}

__global__ void k_fill(const int* __restrict__ row, const int* __restrict__ col,
                       const float* __restrict__ ea) {
    int e = blockIdx.x * blockDim.x + threadIdx.x;
    if (e >= EE) return;
    int r = row[e];
    int idx = atomicAdd(&g_cursor[r], 1);
    g_ccol[idx] = col[e];
    g_cea[idx]  = ea[e];
}

// hop 0 fused (u==0): warp per node; lanes split edges for third term; emit bf16 u.
__global__ void k_hop0(const float* __restrict__ x,
                       const float* __restrict__ l3w, const float* __restrict__ l3b,
                       const float* __restrict__ l0w, const float* __restrict__ l0b,
                       const float* __restrict__ l1b,
                       const float* __restrict__ l2w, const float* __restrict__ l2b) {
    int warp = threadIdx.x >> 5, lane = threadIdx.x & 31;
    int n = blockIdx.x * 8 + warp;
    if (n >= NN) return;
    float w = l3w[0], b = l3b[0];
    int s = g_start[n], e = g_start[n + 1];
    float acc = 0.f;
    for (int t = s + lane; t < e; t += 32) acc += fmaxf(g_cea[t] * w + b, 0.f);
    for (int o = 16; o; o >>= 1) acc += __shfl_xor_sync(0xffffffffu, acc, o);
    float third = (e > s) ? acc / (float)(e - s) : 0.f;
    float xv = x[n];
    int h0 = lane * 4;
    float v0 = xv * l0w[h0]     + third * l2w[h0]     + l0b[h0]     + l1b[h0]     + l2b[h0];
    float v1 = xv * l0w[h0 + 1] + third * l2w[h0 + 1] + l0b[h0 + 1] + l1b[h0 + 1] + l2b[h0 + 1];
    float v2 = xv * l0w[h0 + 2] + third * l2w[h0 + 2] + l0b[h0 + 2] + l1b[h0 + 2] + l2b[h0 + 2];
    float v3 = xv * l0w[h0 + 3] + third * l2w[h0 + 3] + l0b[h0 + 3] + l1b[h0 + 3] + l2b[h0 + 3];
    __nv_bfloat162 lo = __floats2bfloat162_rn(fmaxf(v0, 0.f), fmaxf(v1, 0.f));
    __nv_bfloat162 hi = __floats2bfloat162_rn(fmaxf(v2, 0.f), fmaxf(v3, 0.f));
    uint2 pk;
    pk.x = *reinterpret_cast<unsigned*>(&lo);
    pk.y = *reinterpret_cast<unsigned*>(&hi);
    reinterpret_cast<uint2*>(g_ub)[(size_t)n * 32 + lane] = pk;
}

// edge aggregation: warp per node, CSR gather from bf16 rows (256 B/edge), 4-edge unroll.
__global__ void k_gather(const float* __restrict__ l3w, const float* __restrict__ l3b) {
    int warp = threadIdx.x >> 5, lane = threadIdx.x & 31;
    int n = blockIdx.x * 8 + warp;
    if (n >= NN) return;
    const uint2* ub = reinterpret_cast<const uint2*>(g_ub);  // 8 B = 4 bf16 per lane
    float w = l3w[0], b = l3b[0];
    int s = g_start[n], e = g_start[n + 1];
    float ax = 0.f, ay = 0.f, az = 0.f, aw = 0.f, tacc = 0.f;
    int t = s;
    for (; t + 3 < e; t += 4) {
        int c0 = g_ccol[t], c1 = g_ccol[t + 1], c2 = g_ccol[t + 2], c3 = g_ccol[t + 3];
        float a0 = g_cea[t], a1 = g_cea[t + 1], a2 = g_cea[t + 2], a3 = g_cea[t + 3];
        uint2 r0 = ub[(size_t)c0 * 32 + lane];
        uint2 r1 = ub[(size_t)c1 * 32 + lane];
        uint2 r2 = ub[(size_t)c2 * 32 + lane];
        uint2 r3 = ub[(size_t)c3 * 32 + lane];
        float2 p0 = __bfloat1622float2(*reinterpret_cast<__nv_bfloat162*>(&r0.x));
        float2 q0 = __bfloat1622float2(*reinterpret_cast<__nv_bfloat162*>(&r0.y));
        float2 p1 = __bfloat1622float2(*reinterpret_cast<__nv_bfloat162*>(&r1.x));
        float2 q1 = __bfloat1622float2(*reinterpret_cast<__nv_bfloat162*>(&r1.y));
        float2 p2 = __bfloat1622float2(*reinterpret_cast<__nv_bfloat162*>(&r2.x));
        float2 q2 = __bfloat1622float2(*reinterpret_cast<__nv_bfloat162*>(&r2.y));
        float2 p3 = __bfloat1622float2(*reinterpret_cast<__nv_bfloat162*>(&r3.x));
        float2 q3 = __bfloat1622float2(*reinterpret_cast<__nv_bfloat162*>(&r3.y));
        ax += a0 * p0.x + a1 * p1.x + a2 * p2.x + a3 * p3.x;
        ay += a0 * p0.y + a1 * p1.y + a2 * p2.y + a3 * p3.y;
        az += a0 * q0.x + a1 * q1.x + a2 * q2.x + a3 * q3.x;
        aw += a0 * q0.y + a1 * q1.y + a2 * q2.y + a3 * q3.y;
        tacc += fmaxf(a0 * w + b, 0.f) + fmaxf(a1 * w + b, 0.f)
              + fmaxf(a2 * w + b, 0.f) + fmaxf(a3 * w + b, 0.f);
    }
    for (; t < e; t++) {
        int c0 = g_ccol[t];
        float a0 = g_cea[t];
        uint2 r0 = ub[(size_t)c0 * 32 + lane];
        float2 p0 = __bfloat1622float2(*reinterpret_cast<__nv_bfloat162*>(&r0.x));
        float2 q0 = __bfloat1622float2(*reinterpret_cast<__nv_bfloat162*>(&r0.y));
        ax += a0 * p0.x; ay += a0 * p0.y; az += a0 * q0.x; aw += a0 * q0.y;
        tacc += fmaxf(a0 * w + b, 0.f);
    }
    float inv = (e > s) ? 1.f / (float)(e - s) : 0.f;
    float4 out = make_float4(ax * inv, ay * inv, az * inv, aw * inv);
    *reinterpret_cast<float4*>(&g_mean[(size_t)n * HH + lane * 4]) = out;
    if (lane == 0) g_third[n] = tacc * inv;
}

// node matmul + fused hop update (FFMA2, warp-broadcast A).
// mode 0: emit bf16 only (intermediate hop); mode 1: emit fp32 only (last hop).
__global__ __launch_bounds__(256) void k_mm(
    const float* __restrict__ x, const float* __restrict__ W1,
    const float* __restrict__ l0w, const float* __restrict__ l2w,
    const float* __restrict__ b0, const float* __restrict__ b1,
    const float* __restrict__ b2, int mode) {
    extern __shared__ float sm[];
    float* sW  = sm;            // [128][128] row = k
    float* sAT = sm + HH * HH;  // [128][AST] row = k (transposed A)
    int tid = threadIdx.x;

    const float4* W4 = reinterpret_cast<const float4*>(W1);
    float4* sW4 = reinterpret_cast<float4*>(sW);
    #pragma unroll
    for (int i = tid; i < HH * HH / 4; i += 256) sW4[i] = W4[i];

    int n0 = blockIdx.x * MMJ;
    #pragma unroll
    for (int i = tid; i < MMJ * HH; i += 256) {
        int h = i & 127, j = i >> 7;
        int n = n0 + j;
        sAT[h * AST + j] = (n < NN) ? g_mean[(size_t)n * HH + h] : 0.f;
    }
    __syncthreads();

    int lane = tid & 31, warp = tid >> 5;
    int c0 = lane * 4, j0 = warp * 8;

    u64 acc[8][2];
    #pragma unroll
    for (int r = 0; r < 8; r++) { acc[r][0] = 0ULL; acc[r][1] = 0ULL; }

    #pragma unroll 4
    for (int k = 0; k < HH; k++) {
        float4 av0 = *reinterpret_cast<const float4*>(&sAT[k * AST + j0]);      // broadcast
        float4 av1 = *reinterpret_cast<const float4*>(&sAT[k * AST + j0 + 4]);  // broadcast
        const u64* wrow = reinterpret_cast<const u64*>(&sW[k * HH + c0]);
        u64 w0 = wrow[0], w1 = wrow[1];
        u64 ad[8];
        ad[0] = dupf(av0.x); ad[1] = dupf(av0.y); ad[2] = dupf(av0.z); ad[3] = dupf(av0.w);
        ad[4] = dupf(av1.x); ad[5] = dupf(av1.y); ad[6] = dupf(av1.z); ad[7] = dupf(av1.w);
        #pragma unroll
        for (int r = 0; r < 8; r++) {
            acc[r][0] = ffma2(ad[r], w0, acc[r][0]);
            acc[r][1] = ffma2(ad[r], w1, acc[r][1]);
        }
    }

    float4 w0v = *reinterpret_cast<const float4*>(&l0w[c0]);
    float4 w2v = *reinterpret_cast<const float4*>(&l2w[c0]);
    float4 p0 = *reinterpret_cast<const float4*>(&b0[c0]);
    float4 p1 = *reinterpret_cast<const float4*>(&b1[c0]);
    float4 p2 = *reinterpret_cast<const float4*>(&b2[c0]);
    float bias0 = p0.x + p1.x + p2.x, bias1 = p0.y + p1.y + p2.y;
    float bias2 = p0.z + p1.z + p2.z, bias3 = p0.w + p1.w + p2.w;

    uint2* ub = reinterpret_cast<uint2*>(g_ub);
    #pragma unroll
    for (int r = 0; r < 8; r++) {
        int n = n0 + j0 + r;
        if (n < NN) {
            float xv = x[n], tv = g_third[n];
            float2 f0 = *reinterpret_cast<float2*>(&acc[r][0]);
            float2 f1 = *reinterpret_cast<float2*>(&acc[r][1]);
            float4 o;
            o.x = fmaxf(xv * w0v.x + tv * w2v.x + bias0 + f0.x, 0.f);
            o.y = fmaxf(xv * w0v.y + tv * w2v.y + bias1 + f0.y, 0.f);
            o.z = fmaxf(xv * w0v.z + tv * w2v.z + bias2 + f1.x, 0.f);
            o.w = fmaxf(xv * w0v.w + tv * w2v.w + bias3 + f1.y, 0.f);
            if (mode == 0) {
                __nv_bfloat162 lo = __floats2bfloat162_rn(o.x, o.y);
                __nv_bfloat162 hi = __floats2bfloat162_rn(o.z, o.w);
                uint2 pk;
                pk.x = *reinterpret_cast<unsigned*>(&lo);
                pk.y = *reinterpret_cast<unsigned*>(&hi);
                ub[(size_t)n * 32 + lane] = pk;
            } else {
                *reinterpret_cast<float4*>(&g_u[(size_t)n * HH + c0]) = o;
            }
        }
    }
}

// per-graph pooled sums (batch sorted -> register accumulate, flush on change)
__global__ void k_pool(const float* __restrict__ x, const int* __restrict__ batch) {
    int h = threadIdx.x;               // 128
    int n0 = blockIdx.x * 128;
    if (n0 >= NN) return;
    int n1 = n0 + 128; if (n1 > NN) n1 = NN;
    int gcur = batch[n0];
    float a0 = 0.f, a1 = 0.f, c0 = 0.f, c1 = 0.f;
    for (int n = n0; n < n1; n++) {
        int g = batch[n];
        if (g != gcur) {
            atomicAdd(&g_gs0[gcur * HH + h], a0);
            atomicAdd(&g_gs1[gcur * HH + h], a1);
            if (h == 0) { atomicAdd(&g_cnt[gcur], c0); atomicAdd(&g_cnt[BB + gcur], c1); }
            a0 = a1 = c0 = c1 = 0.f;
            gcur = g;
        }
        float xv = x[n];
        float uv = g_u[(size_t)n * HH + h];
        a0 += uv * (1.f - xv); a1 += uv * xv;
        c0 += 1.f - xv;        c1 += xv;
    }
    atomicAdd(&g_gs0[gcur * HH + h], a0);
    atomicAdd(&g_gs1[gcur * HH + h], a1);
    if (h == 0) { atomicAdd(&g_cnt[gcur], c0); atomicAdd(&g_cnt[BB + gcur], c1); }
}

// per-graph: hc0/hc1, folded attention vectors v0/v1 = att_w @ hc, and 10 scalars
__global__ void k_graph(const float* __restrict__ attw, const float* __restrict__ attb) {
    __shared__ float hc0[HH], hc1[HH], v0[2 * HH], v1[2 * HH];
    int g = blockIdx.x, t = threadIdx.x;  // 256 threads
    if (t < HH) {
        float c0 = g_cnt[g], c1 = g_cnt[BB + g];
        hc0[t] = (c0 > 0.f) ? g_gs0[g * HH + t] / c0 : 0.f;
        hc1[t] = (c1 > 0.f) ? g_gs1[g * HH + t] / c1 : 0.f;
    }
    __syncthreads();
    {
        float s0 = 0.f, s1 = 0.f;
        const float* wrow = attw + t * HH;
        for (int j = 0; j < HH; j++) { float w = wrow[j]; s0 += w * hc0[j]; s1 += w * hc1[j]; }
        v0[t] = s0; v1[t] = s1;
        if (t < HH) { g_v0t[g * HH + t] = s0; g_v1t[g * HH + t] = s1; }
    }
    __syncthreads();
    int warp = t >> 5, lane = t & 31;
    for (int id = warp; id < 10; id += 8) {
        const float* vec; const float* hc;
        switch (id) {
            case 0: vec = attb;     hc = hc0; break;  // s0
            case 1: vec = attb;     hc = hc1; break;  // s1
            case 2: vec = g_spvec;  hc = hc0; break;  // p0
            case 3: vec = g_spvec;  hc = hc1; break;  // p1
            case 4: vec = g_acbot;  hc = hc0; break;  // a0
            case 5: vec = g_acbot;  hc = hc1; break;  // a1
            case 6: vec = v0 + HH;  hc = hc0; break;  // d00
            case 7: vec = v0 + HH;  hc = hc1; break;  // d01
            case 8: vec = v1 + HH;  hc = hc0; break;  // d10
            default: vec = v1 + HH; hc = hc1; break;  // d11
        }
        float s = 0.f;
        for (int j = lane; j < HH; j += 32) s += vec[j] * hc[j];
        for (int o = 16; o; o >>= 1) s += __shfl_down_sync(0xffffffffu, s, o);
        if (lane == 0) g_scal[g * 10 + id] = s;
    }
}

// per-node head: 3 dots of length 128 + softmax over 2 + folded output
__global__ void k_final(const float* __restrict__ x, const int* __restrict__ batch,
                        float* __restrict__ out) {
    int warp = threadIdx.x >> 5, lane = threadIdx.x & 31;
    int n = blockIdx.x * 8 + warp;
    if (n >= NN) return;
    int g = batch[n];
    float4 uv = *reinterpret_cast<const float4*>(&g_u[(size_t)n * HH + lane * 4]);
    float4 vA = *reinterpret_cast<const float4*>(&g_v0t[g * HH + lane * 4]);
    float4 vB = *reinterpret_cast<const float4*>(&g_v1t[g * HH + lane * 4]);
    float4 vC = *reinterpret_cast<const float4*>(&g_actop[lane * 4]);
    float da = uv.x * vA.x + uv.y * vA.y + uv.z * vA.z + uv.w * vA.w;
    float db = uv.x * vB.x + uv.y * vB.y + uv.z * vB.z + uv.w * vB.w;
    float dc = uv.x * vC.x + uv.y * vC.y + uv.z * vC.z + uv.w * vC.w;
    for (int o = 16; o; o >>= 1) {
        da += __shfl_down_sync(0xffffffffu, da, o);
        db += __shfl_down_sync(0xffffffffu, db, o);
        dc += __shfl_down_sync(0xffffffffu, dc, o);
    }
    if (lane == 0) {
        const float* sc = &g_scal[g * 10];
        bool xb = x[n] > 0.5f;
        float w0 = da + (xb ? sc[6] : sc[7]) + sc[0];
        float w1 = db + (xb ? sc[8] : sc[9]) + sc[1];
        float m = fmaxf(w0, w1);
        float e0 = __expf(w0 - m), e1 = __expf(w1 - m);
        float sw = e0 / (e0 + e1);
        out[n] = sw * sc[2] + (1.f - sw) * sc[3] + dc + (xb ? sc[4] : sc[5]) + g_c0;
    }
}

// ---------------- launch ----------------
extern "C" void kernel_launch(void* const* d_in, const int* in_sizes, int n_in,
                              void* d_out, int out_size) {
    int base = (n_in >= 21) ? 5 : 4;
    const float* x     = (const float*)d_in[0];
    const int*   ei    = (const int*)d_in[1];
    const float* ea    = (const float*)d_in[2];
    const int*   batch = (const int*)d_in[3];
    const float* l0w   = (const float*)d_in[base + 0];
    const float* l0b   = (const float*)d_in[base + 1];
    const float* l1w   = (const float*)d_in[base + 2];
    const float* l1b   = (const float*)d_in[base + 3];
    const float* l2w   = (const float*)d_in[base + 4];
    const float* l2b   = (const float*)d_in[base + 5];
    const float* l3w   = (const float*)d_in[base + 6];
    const float* l3b   = (const float*)d_in[base + 7];
    const float* attw  = (const float*)d_in[base + 8];
    const float* attb  = (const float*)d_in[base + 9];
    const float* spw   = (const float*)d_in[base + 10];
    const float* spb   = (const float*)d_in[base + 11];
    const float* acw   = (const float*)d_in[base + 12];
    const float* acb   = (const float*)d_in[base + 13];
    const float* lastw = (const float*)d_in[base + 14];
    const float* lastb = (const float*)d_in[base + 15];
    const int* row = ei;
    const int* col = ei + EE;
    float* out = (float*)d_out;

    const int SMEM_MM = (HH * HH + HH * AST) * (int)sizeof(float);  // 100352 B
    cudaFuncSetAttribute(k_mm, cudaFuncAttributeMaxDynamicSharedMemorySize, SMEM_MM);

    k_zero<<<(NN + 255) / 256, 256>>>(spw, spb, acw, acb, lastw, lastb);
    k_hist<<<(EE + 255) / 256, 256>>>(row);
    k_scan1<<<NB1, 256>>>();
    k_scan3<<<NB1, 256>>>();
    k_fill<<<(EE + 255) / 256, 256>>>(row, col, ea);

    // hop 0 (u == 0): fused third+update, bf16 out
    k_hop0<<<(NN + 7) / 8, 256>>>(x, l3w, l3b, l0w, l0b, l1b, l2w, l2b);

    // hop 1 (bf16 out), hop 2 (fp32 out)
    for (int i = 1; i < 3; i++) {
        k_gather<<<(NN + 7) / 8, 256>>>(l3w + i, l3b + i);
        k_mm<<<(NN + MMJ - 1) / MMJ, 256, SMEM_MM>>>(x, l1w + i * HH * HH,
                                        l0w + i * HH, l2w + i * HH,
                                        l0b + i * HH, l1b + i * HH, l2b + i * HH,
                                        (i == 2) ? 1 : 0);
    }

    k_pool<<<(NN + 127) / 128, 128>>>(x, batch);
    k_graph<<<BB, 256>>>(attw, attb);
    k_final<<<NN / 8, 256>>>(x, batch, out);
}

// round 10
// speedup vs baseline: 1.3860x; 1.2779x over previous
#include <cuda_runtime.h>
#include <cuda_bf16.h>
#include <cstdint>

#define NN 100000
#define EE 800000
#define HH 128
#define BB 64
#define NB1 196   // ceil(NN/512)

// ---------------- scratch (device globals: no runtime allocation) ----------------
__device__ float g_u[(size_t)NN * HH];           // hop-2 node features (fp32, head path)
__device__ __nv_bfloat162 g_ub[(size_t)NN * 64]; // bf16 u (gather input)
__device__ uint2 g_meanb[(size_t)NN * 32];       // bf16 seg-mean rows (mma A input)
__device__ __nv_bfloat16 g_wtb[2 * HH * HH];     // bf16 W^T for hops 1,2  [c][k]
__device__ float g_third[NN];                    // seg_mean(ee) per node (per hop)
__device__ int   g_deg[NN];
__device__ int   g_start[NN + 1];
__device__ int   g_cursor[NN];
__device__ int   g_bsum[NB1 + 4];
__device__ int   g_ccol[EE];
__device__ float g_cea[EE];
__device__ float g_gs0[BB * HH], g_gs1[BB * HH];
__device__ float g_cnt[2 * BB];
__device__ float g_v0t[BB * HH], g_v1t[BB * HH];
__device__ float g_scal[BB * 10];                // s0,s1,p0,p1,a0,a1,d00,d01,d10,d11
__device__ float g_spvec[HH], g_actop[HH], g_acbot[HH];
__device__ float g_c0;

__device__ __forceinline__ uint32_t smem_u32(const void* p) {
    uint32_t a;
    asm("{ .reg .u64 t; cvta.to.shared.u64 t, %1; cvt.u32.u64 %0, t; }" : "=r"(a) : "l"(p));
    return a;
}

// smem layout for k_hmma (bf16, rows padded to 136 elems = 272 B)
#define ASTB 136
#define SH_A 0
#define SH_B (128 * ASTB * 2)            // 34816
#define SH_CB (2 * 128 * ASTB * 2)       // 69632
#define SH_C0 (SH_CB + 512)
#define SH_C2 (SH_C0 + 512)
#define SH_TOTAL (SH_C2 + 512)           // 71168

// ---------------- zero + folded final-layer vectors (merged) ----------------
__global__ void k_zero(const float* __restrict__ spw, const float* __restrict__ spb,
                       const float* __restrict__ acw, const float* __restrict__ acb,
                       const float* __restrict__ lastw, const float* __restrict__ lastb) {
    int i = blockIdx.x * blockDim.x + threadIdx.x;
    if (i < NN) g_deg[i] = 0;
    if (i < BB * HH) { g_gs0[i] = 0.f; g_gs1[i] = 0.f; }
    if (i < 2 * BB) { g_cnt[i] = 0.f; }
    if (i == 0) g_start[NN] = EE;
    if (blockIdx.x == 0) {
        int t = threadIdx.x;  // 256
        if (t < HH) {
            float s = 0.f;
            for (int j = 0; j < HH; j++) s += spw[t * HH + j] * lastw[j];
            g_spvec[t] = s;
        }
        {
            float s = 0.f;
            for (int j = 0; j < HH; j++) s += acw[t * HH + j] * lastw[HH + j];
            if (t < HH) g_actop[t] = s; else g_acbot[t - HH] = s;
        }
        if (t < 32) {
            float s = 0.f;
            for (int j = t; j < HH; j += 32) s += spb[j] * lastw[j] + acb[j] * lastw[HH + j];
            for (int o = 16; o; o >>= 1) s += __shfl_down_sync(0xffffffffu, s, o);
            if (t == 0) g_c0 = s + lastb[0];
        }
    }
}

__global__ void k_hist(const int* __restrict__ row) {
    int e = blockIdx.x * blockDim.x + threadIdx.x;
    if (e < EE) atomicAdd(&g_deg[row[e]], 1);
}

// ---- scan ----
__global__ void k_scan1() {
    int t = threadIdx.x;                     // 256 threads, 512 nodes/block
    int n0 = blockIdx.x * 512;
    int s = 0;
    int i = n0 + t;
    if (i < NN) s += g_deg[i];
    if (i + 256 < n0 + 512 && i + 256 < NN) s += g_deg[i + 256];
    int lane = t & 31, warp = t >> 5;
    for (int o = 16; o; o >>= 1) s += __shfl_down_sync(0xffffffffu, s, o);
    __shared__ int ws[8];
    if (lane == 0) ws[warp] = s;
    __syncthreads();
    if (t == 0) {
        int tot = 0;
        #pragma unroll
        for (int w = 0; w < 8; w++) tot += ws[w];
        g_bsum[blockIdx.x] = tot;
    }
}

__global__ void k_scan3() {
    int t = threadIdx.x, blk = blockIdx.x;   // 256 threads
    __shared__ int ws[8], wo[8], sBoff;
    int lane = t & 31, warp = t >> 5;

    int bv = (t < blk) ? g_bsum[t] : 0;
    for (int o = 16; o; o >>= 1) bv += __shfl_down_sync(0xffffffffu, bv, o);
    if (lane == 0) ws[warp] = bv;
    __syncthreads();
    if (t == 0) {
        int tot = 0;
        #pragma unroll
        for (int w = 0; w < 8; w++) tot += ws[w];
        sBoff = tot;
    }
    __syncthreads();

    int i0 = blk * 512 + t * 2;
    int d0 = (i0 < NN) ? g_deg[i0] : 0;
    int d1 = (i0 + 1 < NN) ? g_deg[i0 + 1] : 0;
    int s = d0 + d1;
    int v = s;
    for (int o = 1; o < 32; o <<= 1) {
        int u = __shfl_up_sync(0xffffffffu, v, o);
        if (lane >= o) v += u;
    }
    if (lane == 31) ws[warp] = v;
    __syncthreads();
    if (t == 0) {
        int run = 0;
        #pragma unroll
        for (int w = 0; w < 8; w++) { wo[w] = run; run += ws[w]; }
    }
    __syncthreads();
    int ex = v - s + wo[warp] + sBoff;
    if (i0 < NN)     { g_start[i0] = ex;          g_cursor[i0] = ex; }
    if (i0 + 1 < NN) { g_start[i0 + 1] = ex + d0; g_cursor[i0 + 1] = ex + d0; }
}

__global__ void k_fill(const int* __restrict__ row, const int* __restrict__ col,
                       const float* __restrict__ ea) {
    int e = blockIdx.x * blockDim.x + threadIdx.x;
    if (e >= EE) return;
    int r = row[e];
    int idx = atomicAdd(&g_cursor[r], 1);
    g_ccol[idx] = col[e];
    g_cea[idx]  = ea[e];
}

// W^T -> bf16 for hops 1,2: g_wtb[(hop-1)][c][k] = bf16(W[hop][k][c])
__global__ void k_wt(const float* __restrict__ l1w) {
    int i = blockIdx.x * blockDim.x + threadIdx.x;   // 2*128*128
    if (i >= 2 * HH * HH) return;
    int hop = i >> 14;
    int c = (i >> 7) & 127;
    int k = i & 127;
    g_wtb[i] = __float2bfloat16(l1w[(hop + 1) * HH * HH + k * HH + c]);
}

// hop 0 fused (u==0): warp per node; lanes split edges for third term; emit bf16 u.
__global__ void k_hop0(const float* __restrict__ x,
                       const float* __restrict__ l3w, const float* __restrict__ l3b,
                       const float* __restrict__ l0w, const float* __restrict__ l0b,
                       const float* __restrict__ l1b,
                       const float* __restrict__ l2w, const float* __restrict__ l2b) {
    int warp = threadIdx.x >> 5, lane = threadIdx.x & 31;
    int n = blockIdx.x * 8 + warp;
    if (n >= NN) return;
    float w = l3w[0], b = l3b[0];
    int s = g_start[n], e = g_start[n + 1];
    float acc = 0.f;
    for (int t = s + lane; t < e; t += 32) acc += fmaxf(g_cea[t] * w + b, 0.f);
    for (int o = 16; o; o >>= 1) acc += __shfl_xor_sync(0xffffffffu, acc, o);
    float third = (e > s) ? acc / (float)(e - s) : 0.f;
    float xv = x[n];
    int h0 = lane * 4;
    float v0 = xv * l0w[h0]     + third * l2w[h0]     + l0b[h0]     + l1b[h0]     + l2b[h0];
    float v1 = xv * l0w[h0 + 1] + third * l2w[h0 + 1] + l0b[h0 + 1] + l1b[h0 + 1] + l2b[h0 + 1];
    float v2 = xv * l0w[h0 + 2] + third * l2w[h0 + 2] + l0b[h0 + 2] + l1b[h0 + 2] + l2b[h0 + 2];
    float v3 = xv * l0w[h0 + 3] + third * l2w[h0 + 3] + l0b[h0 + 3] + l1b[h0 + 3] + l2b[h0 + 3];
    __nv_bfloat162 lo = __floats2bfloat162_rn(fmaxf(v0, 0.f), fmaxf(v1, 0.f));
    __nv_bfloat162 hi = __floats2bfloat162_rn(fmaxf(v2, 0.f), fmaxf(v3, 0.f));
    uint2 pk;
    pk.x = *reinterpret_cast<unsigned*>(&lo);
    pk.y = *reinterpret_cast<unsigned*>(&hi);
    reinterpret_cast<uint2*>(g_ub)[(size_t)n * 32 + lane] = pk;
}

// edge aggregation: warp per node, CSR gather from bf16 rows, 4-edge unroll.
// Emits bf16 mean rows (mma A input) + fp32 third.
__global__ void k_gather(const float* __restrict__ l3w, const float* __restrict__ l3b) {
    int warp = threadIdx.x >> 5, lane = threadIdx.x & 31;
    int n = blockIdx.x * 8 + warp;
    if (n >= NN) return;
    const uint2* ub = reinterpret_cast<const uint2*>(g_ub);
    float w = l3w[0], b = l3b[0];
    int s = g_start[n], e = g_start[n + 1];
    float ax = 0.f, ay = 0.f, az = 0.f, aw = 0.f, tacc = 0.f;
    int t = s;
    for (; t + 3 < e; t += 4) {
        int c0 = g_ccol[t], c1 = g_ccol[t + 1], c2 = g_ccol[t + 2], c3 = g_ccol[t + 3];
        float a0 = g_cea[t], a1 = g_cea[t + 1], a2 = g_cea[t + 2], a3 = g_cea[t + 3];
        uint2 r0 = ub[(size_t)c0 * 32 + lane];
        uint2 r1 = ub[(size_t)c1 * 32 + lane];
        uint2 r2 = ub[(size_t)c2 * 32 + lane];
        uint2 r3 = ub[(size_t)c3 * 32 + lane];
        float2 p0 = __bfloat1622float2(*reinterpret_cast<__nv_bfloat162*>(&r0.x));
        float2 q0 = __bfloat1622float2(*reinterpret_cast<__nv_bfloat162*>(&r0.y));
        float2 p1 = __bfloat1622float2(*reinterpret_cast<__nv_bfloat162*>(&r1.x));
        float2 q1 = __bfloat1622float2(*reinterpret_cast<__nv_bfloat162*>(&r1.y));
        float2 p2 = __bfloat1622float2(*reinterpret_cast<__nv_bfloat162*>(&r2.x));
        float2 q2 = __bfloat1622float2(*reinterpret_cast<__nv_bfloat162*>(&r2.y));
        float2 p3 = __bfloat1622float2(*reinterpret_cast<__nv_bfloat162*>(&r3.x));
        float2 q3 = __bfloat1622float2(*reinterpret_cast<__nv_bfloat162*>(&r3.y));
        ax += a0 * p0.x + a1 * p1.x + a2 * p2.x + a3 * p3.x;
        ay += a0 * p0.y + a1 * p1.y + a2 * p2.y + a3 * p3.y;
        az += a0 * q0.x + a1 * q1.x + a2 * q2.x + a3 * q3.x;
        aw += a0 * q0.y + a1 * q1.y + a2 * q2.y + a3 * q3.y;
        tacc += fmaxf(a0 * w + b, 0.f) + fmaxf(a1 * w + b, 0.f)
              + fmaxf(a2 * w + b, 0.f) + fmaxf(a3 * w + b, 0.f);
    }
    for (; t < e; t++) {
        int c0 = g_ccol[t];
        float a0 = g_cea[t];
        uint2 r0 = ub[(size_t)c0 * 32 + lane];
        float2 p0 = __bfloat1622float2(*reinterpret_cast<__nv_bfloat162*>(&r0.x));
        float2 q0 = __bfloat1622float2(*reinterpret_cast<__nv_bfloat162*>(&r0.y));
        ax += a0 * p0.x; ay += a0 * p0.y; az += a0 * q0.x; aw += a0 * q0.y;
        tacc += fmaxf(a0 * w + b, 0.f);
    }
    float inv = (e > s) ? 1.f / (float)(e - s) : 0.f;
    __nv_bfloat162 lo = __floats2bfloat162_rn(ax * inv, ay * inv);
    __nv_bfloat162 hi = __floats2bfloat162_rn(az * inv, aw * inv);
    uint2 pk;
    pk.x = *reinterpret_cast<unsigned*>(&lo);
    pk.y = *reinterpret_cast<unsigned*>(&hi);
    g_meanb[(size_t)n * 32 + lane] = pk;
    if (lane == 0) g_third[n] = tacc * inv;
}

// bf16 tensor-core GEMM via mma.sync (base sm_103 ISA) + fused hop epilogue.
// CTA = 128 nodes x 128 cols, K=128. 8 warps; warp w owns rows m0=w*16.
// A[128][K] bf16 smem (pad 136), B^T[c][k] bf16 smem (pad 136).
// mode 0: emit bf16 u; mode 1: emit fp32 g_u.
__global__ __launch_bounds__(256) void k_hmma(
    const float* __restrict__ x,
    const __nv_bfloat16* __restrict__ wtb,   // [128 c][128 k] bf16 row-major
    const float* __restrict__ l0w, const float* __restrict__ l2w,
    const float* __restrict__ b0, const float* __restrict__ b1,
    const float* __restrict__ b2, int mode) {
    extern __shared__ char smem[];
    uint32_t sbase = smem_u32(smem);
    int tid = threadIdx.x, lane = tid & 31, w = tid >> 5;
    int n0g = blockIdx.x * 128;

    // stage A (bf16 mean rows, 8 B per lane-step)
    for (int i = tid; i < 128 * 32; i += 256) {
        int row = i >> 5, u2 = i & 31;
        int n = n0g + row;
        uint2 v = (n < NN) ? g_meanb[(size_t)n * 32 + u2] : make_uint2(0u, 0u);
        *reinterpret_cast<uint2*>(smem + SH_A + row * (ASTB * 2) + u2 * 8) = v;
    }
    // stage B^T
    const uint2* wb = reinterpret_cast<const uint2*>(wtb);
    for (int i = tid; i < 128 * 32; i += 256) {
        int row = i >> 5, u2 = i & 31;
        *reinterpret_cast<uint2*>(smem + SH_B + row * (ASTB * 2) + u2 * 8) = wb[row * 32 + u2];
    }
    if (tid < 128) {
        reinterpret_cast<float*>(smem + SH_CB)[tid] = b0[tid] + b1[tid] + b2[tid];
        reinterpret_cast<float*>(smem + SH_C0)[tid] = l0w[tid];
        reinterpret_cast<float*>(smem + SH_C2)[tid] = l2w[tid];
    }
    __syncthreads();

    // ldmatrix lane addressing
    int lg = lane >> 3, li = lane & 7;
    int rowA = w * 16 + (lg & 1) * 8 + li;          // A rows for this warp
    uint32_t aBase = sbase + SH_A + rowA * (ASTB * 2) + ((lg >> 1) * 8) * 2;
    int rowBb = (lg >> 1) * 8 + li;                 // B row base within n-tile pair
    uint32_t bBase = sbase + SH_B + rowBb * (ASTB * 2) + ((lg & 1) * 8) * 2;

    float acc[16][4];
    #pragma unroll
    for (int t = 0; t < 16; t++)
        #pragma unroll
        for (int j = 0; j < 4; j++) acc[t][j] = 0.f;

    #pragma unroll 1
    for (int ks = 0; ks < 8; ks++) {
        uint32_t kb2 = ks * 32;   // kb*2 bytes
        uint32_t a0, a1, a2, a3;
        asm volatile("ldmatrix.sync.aligned.m8n8.x4.shared.b16 {%0,%1,%2,%3}, [%4];"
                     : "=r"(a0), "=r"(a1), "=r"(a2), "=r"(a3) : "r"(aBase + kb2));
        #pragma unroll
        for (int np = 0; np < 8; np++) {
            uint32_t r0, r1, r2, r3;
            asm volatile("ldmatrix.sync.aligned.m8n8.x4.shared.b16 {%0,%1,%2,%3}, [%4];"
                         : "=r"(r0), "=r"(r1), "=r"(r2), "=r"(r3)
                         : "r"(bBase + np * 16 * (ASTB * 2) + kb2));
            asm volatile(
                "mma.sync.aligned.m16n8k16.row.col.f32.bf16.bf16.f32 "
                "{%0,%1,%2,%3}, {%4,%5,%6,%7}, {%8,%9}, {%0,%1,%2,%3};"
                : "+f"(acc[2 * np][0]), "+f"(acc[2 * np][1]),
                  "+f"(acc[2 * np][2]), "+f"(acc[2 * np][3])
                : "r"(a0), "r"(a1), "r"(a2), "r"(a3), "r"(r0), "r"(r1));
            asm volatile(
                "mma.sync.aligned.m16n8k16.row.col.f32.bf16.bf16.f32 "
                "{%0,%1,%2,%3}, {%4,%5,%6,%7}, {%8,%9}, {%0,%1,%2,%3};"
                : "+f"(acc[2 * np + 1][0]), "+f"(acc[2 * np + 1][1]),
                  "+f"(acc[2 * np + 1][2]), "+f"(acc[2 * np + 1][3])
                : "r"(a0), "r"(a1), "r"(a2), "r"(a3), "r"(r2), "r"(r3));
        }
    }

    // epilogue: thread holds rows (m0 + lane/4) and (+8), cols 8t + (lane%4)*2, +1
    int q = lane & 3;
    int row0 = w * 16 + (lane >> 2), row1 = row0 + 8;
    int nA = n0g + row0, nB = n0g + row1;
    float xA = 0.f, tA = 0.f, xB = 0.f, tB = 0.f;
    if (nA < NN) { xA = x[nA]; tA = g_third[nA]; }
    if (nB < NN) { xB = x[nB]; tB = g_third[nB]; }
    const float* sCB = reinterpret_cast<const float*>(smem + SH_CB);
    const float* sC0 = reinterpret_cast<const float*>(smem + SH_C0);
    const float* sC2 = reinterpret_cast<const float*>(smem + SH_C2);

    #pragma unroll
    for (int t = 0; t < 16; t++) {
        int c = t * 8 + q * 2;
        float2 bb = *reinterpret_cast<const float2*>(&sCB[c]);
        float2 w0 = *reinterpret_cast<const float2*>(&sC0[c]);
        float2 w2 = *reinterpret_cast<const float2*>(&sC2[c]);
        float oA0 = fmaxf(xA * w0.x + tA * w2.x + bb.x + acc[t][0], 0.f);
        float oA1 = fmaxf(xA * w0.y + tA * w2.y + bb.y + acc[t][1], 0.f);
        float oB0 = fmaxf(xB * w0.x + tB * w2.x + bb.x + acc[t][2], 0.f);
        float oB1 = fmaxf(xB * w0.y + tB * w2.y + bb.y + acc[t][3], 0.f);
        if (mode == 1) {
            if (nA < NN) *reinterpret_cast<float2*>(&g_u[(size_t)nA * HH + c]) = make_float2(oA0, oA1);
            if (nB < NN) *reinterpret_cast<float2*>(&g_u[(size_t)nB * HH + c]) = make_float2(oB0, oB1);
        } else {
            if (nA < NN) g_ub[(size_t)nA * 64 + (c >> 1)] = __floats2bfloat162_rn(oA0, oA1);
            if (nB < NN) g_ub[(size_t)nB * 64 + (c >> 1)] = __floats2bfloat162_rn(oB0, oB1);
        }
    }
}

// per-graph pooled sums (batch sorted -> register accumulate, flush on change)
__global__ void k_pool(const float* __restrict__ x, const int* __restrict__ batch) {
    int h = threadIdx.x;               // 128
    int n0 = blockIdx.x * 128;
    if (n0 >= NN) return;
    int n1 = n0 + 128; if (n1 > NN) n1 = NN;
    int gcur = batch[n0];
    float a0 = 0.f, a1 = 0.f, c0 = 0.f, c1 = 0.f;
    for (int n = n0; n < n1; n++) {
        int g = batch[n];
        if (g != gcur) {
            atomicAdd(&g_gs0[gcur * HH + h], a0);
            atomicAdd(&g_gs1[gcur * HH + h], a1);
            if (h == 0) { atomicAdd(&g_cnt[gcur], c0); atomicAdd(&g_cnt[BB + gcur], c1); }
            a0 = a1 = c0 = c1 = 0.f;
            gcur = g;
        }
        float xv = x[n];
        float uv = g_u[(size_t)n * HH + h];
        a0 += uv * (1.f - xv); a1 += uv * xv;
        c0 += 1.f - xv;        c1 += xv;
    }
    atomicAdd(&g_gs0[gcur * HH + h], a0);
    atomicAdd(&g_gs1[gcur * HH + h], a1);
    if (h == 0) { atomicAdd(&g_cnt[gcur], c0); atomicAdd(&g_cnt[BB + gcur], c1); }
}

// per-graph: hc0/hc1, folded attention vectors v0/v1 = att_w @ hc, and 10 scalars
__global__ void k_graph(const float* __restrict__ attw, const float* __restrict__ attb) {
    __shared__ float hc0[HH], hc1[HH], v0[2 * HH], v1[2 * HH];
    int g = blockIdx.x, t = threadIdx.x;  // 256 threads
    if (t < HH) {
        float c0 = g_cnt[g], c1 = g_cnt[BB + g];
        hc0[t] = (c0 > 0.f) ? g_gs0[g * HH + t] / c0 : 0.f;
        hc1[t] = (c1 > 0.f) ? g_gs1[g * HH + t] / c1 : 0.f;
    }
    __syncthreads();
    {
        float s0 = 0.f, s1 = 0.f;
        const float* wrow = attw + t * HH;
        for (int j = 0; j < HH; j++) { float w = wrow[j]; s0 += w * hc0[j]; s1 += w * hc1[j]; }
        v0[t] = s0; v1[t] = s1;
        if (t < HH) { g_v0t[g * HH + t] = s0; g_v1t[g * HH + t] = s1; }
    }
    __syncthreads();
    int warp = t >> 5, lane = t & 31;
    for (int id = warp; id < 10; id += 8) {
        const float* vec; const float* hc;
        switch (id) {
            case 0: vec = attb;     hc = hc0; break;  // s0
            case 1: vec = attb;     hc = hc1; break;  // s1
            case 2: vec = g_spvec;  hc = hc0; break;  // p0
            case 3: vec = g_spvec;  hc = hc1; break;  // p1
            case 4: vec = g_acbot;  hc = hc0; break;  // a0
            case 5: vec = g_acbot;  hc = hc1; break;  // a1
            case 6: vec = v0 + HH;  hc = hc0; break;  // d00
            case 7: vec = v0 + HH;  hc = hc1; break;  // d01
            case 8: vec = v1 + HH;  hc = hc0; break;  // d10
            default: vec = v1 + HH; hc = hc1; break;  // d11
        }
        float s = 0.f;
        for (int j = lane; j < HH; j += 32) s += vec[j] * hc[j];
        for (int o = 16; o; o >>= 1) s += __shfl_down_sync(0xffffffffu, s, o);
        if (lane == 0) g_scal[g * 10 + id] = s;
    }
}

// per-node head: 3 dots of length 128 + softmax over 2 + folded output
__global__ void k_final(const float* __restrict__ x, const int* __restrict__ batch,
                        float* __restrict__ out) {
    int warp = threadIdx.x >> 5, lane = threadIdx.x & 31;
    int n = blockIdx.x * 8 + warp;
    if (n >= NN) return;
    int g = batch[n];
    float4 uv = *reinterpret_cast<const float4*>(&g_u[(size_t)n * HH + lane * 4]);
    float4 vA = *reinterpret_cast<const float4*>(&g_v0t[g * HH + lane * 4]);
    float4 vB = *reinterpret_cast<const float4*>(&g_v1t[g * HH + lane * 4]);
    float4 vC = *reinterpret_cast<const float4*>(&g_actop[lane * 4]);
    float da = uv.x * vA.x + uv.y * vA.y + uv.z * vA.z + uv.w * vA.w;
    float db = uv.x * vB.x + uv.y * vB.y + uv.z * vB.z + uv.w * vB.w;
    float dc = uv.x * vC.x + uv.y * vC.y + uv.z * vC.z + uv.w * vC.w;
    for (int o = 16; o; o >>= 1) {
        da += __shfl_down_sync(0xffffffffu, da, o);
        db += __shfl_down_sync(0xffffffffu, db, o);
        dc += __shfl_down_sync(0xffffffffu, dc, o);
    }
    if (lane == 0) {
        const float* sc = &g_scal[g * 10];
        bool xb = x[n] > 0.5f;
        float w0 = da + (xb ? sc[6] : sc[7]) + sc[0];
        float w1 = db + (xb ? sc[8] : sc[9]) + sc[1];
        float m = fmaxf(w0, w1);
        float e0 = __expf(w0 - m), e1 = __expf(w1 - m);
        float sw = e0 / (e0 + e1);
        out[n] = sw * sc[2] + (1.f - sw) * sc[3] + dc + (xb ? sc[4] : sc[5]) + g_c0;
    }
}

// ---------------- launch ----------------
extern "C" void kernel_launch(void* const* d_in, const int* in_sizes, int n_in,
                              void* d_out, int out_size) {
    int base = (n_in >= 21) ? 5 : 4;
    const float* x     = (const float*)d_in[0];
    const int*   ei    = (const int*)d_in[1];
    const float* ea    = (const float*)d_in[2];
    const int*   batch = (const int*)d_in[3];
    const float* l0w   = (const float*)d_in[base + 0];
    const float* l0b   = (const float*)d_in[base + 1];
    const float* l1w   = (const float*)d_in[base + 2];
    const float* l1b   = (const float*)d_in[base + 3];
    const float* l2w   = (const float*)d_in[base + 4];
    const float* l2b   = (const float*)d_in[base + 5];
    const float* l3w   = (const float*)d_in[base + 6];
    const float* l3b   = (const float*)d_in[base + 7];
    const float* attw  = (const float*)d_in[base + 8];
    const float* attb  = (const float*)d_in[base + 9];
    const float* spw   = (const float*)d_in[base + 10];
    const float* spb   = (const float*)d_in[base + 11];
    const float* acw   = (const float*)d_in[base + 12];
    const float* acb   = (const float*)d_in[base + 13];
    const float* lastw = (const float*)d_in[base + 14];
    const float* lastb = (const float*)d_in[base + 15];
    const int* row = ei;
    const int* col = ei + EE;
    float* out = (float*)d_out;

    static __nv_bfloat16* wtb_dev = nullptr;
    if (!wtb_dev) cudaGetSymbolAddress((void**)&wtb_dev, g_wtb);

    cudaFuncSetAttribute(k_hmma, cudaFuncAttributeMaxDynamicSharedMemorySize, SH_TOTAL);

    k_zero<<<(NN + 255) / 256, 256>>>(spw, spb, acw, acb, lastw, lastb);
    k_hist<<<(EE + 255) / 256, 256>>>(row);
    k_scan1<<<NB1, 256>>>();
    k_scan3<<<NB1, 256>>>();
    k_fill<<<(EE + 255) / 256, 256>>>(row, col, ea);
    k_wt<<<(2 * HH * HH + 255) / 256, 256>>>(l1w);

    // hop 0 (u == 0): fused third+update, bf16 out
    k_hop0<<<(NN + 7) / 8, 256>>>(x, l3w, l3b, l0w, l0b, l1b, l2w, l2b);

    // hop 1 (bf16 out), hop 2 (fp32 out): gather then tensor-core GEMM
    for (int i = 1; i < 3; i++) {
        k_gather<<<(NN + 7) / 8, 256>>>(l3w + i, l3b + i);
        k_hmma<<<(NN + 127) / 128, 256, SH_TOTAL>>>(
            x, wtb_dev + (i - 1) * HH * HH,
            l0w + i * HH, l2w + i * HH,
            l0b + i * HH, l1b + i * HH, l2b + i * HH,
            (i == 2) ? 1 : 0);
    }

    k_pool<<<(NN + 127) / 128, 128>>>(x, batch);
    k_graph<<<BB, 256>>>(attw, attb);
    k_final<<<NN / 8, 256>>>(x, batch, out);
}

// round 11
// speedup vs baseline: 1.4693x; 1.0601x over previous
#include <cuda_runtime.h>
#include <cuda_bf16.h>
#include <cstdint>

#define NN 100000
#define EE 800000
#define HH 128
#define BB 64
#define NB1 196   // ceil(NN/512)

// ---------------- scratch (device globals: no runtime allocation) ----------------
__device__ __nv_bfloat162 g_ub[(size_t)NN * 64]; // bf16 u (gather input + head path)
__device__ uint2 g_meanb[(size_t)NN * 32];       // bf16 seg-mean rows (mma A input)
__device__ __nv_bfloat16 g_wtb[2 * HH * HH];     // bf16 W^T for hops 1,2  [c][k]
__device__ float g_third[NN];                    // seg_mean(ee) per node (per hop)
__device__ int   g_deg[NN];
__device__ int   g_start[NN + 1];
__device__ int   g_cursor[NN];
__device__ int   g_bsum[NB1 + 4];
__device__ int   g_ccol[EE];
__device__ float g_cea[EE];
__device__ float g_gs0[BB * HH], g_gs1[BB * HH];
__device__ float g_cnt[2 * BB];
__device__ float g_v0t[BB * HH], g_v1t[BB * HH];
__device__ float g_scal[BB * 10];                // s0,s1,p0,p1,a0,a1,d00,d01,d10,d11
__device__ float g_spvec[HH], g_actop[HH], g_acbot[HH];
__device__ float g_c0;

__device__ __forceinline__ uint32_t smem_u32(const void* p) {
    uint32_t a;
    asm("{ .reg .u64 t; cvta.to.shared.u64 t, %1; cvt.u32.u64 %0, t; }" : "=r"(a) : "l"(p));
    return a;
}

// smem layout for k_hmma (bf16, rows padded to 136 elems = 272 B)
#define ASTB 136
#define SH_A 0
#define SH_B (128 * ASTB * 2)            // 34816
#define SH_CB (2 * 128 * ASTB * 2)       // 69632
#define SH_C0 (SH_CB + 512)
#define SH_C2 (SH_C0 + 512)
#define SH_TOTAL (SH_C2 + 512)           // 71168

// ---------------- zero + folded final-layer vectors + W^T bf16 (merged) ----------------
__global__ void k_zero(const float* __restrict__ spw, const float* __restrict__ spb,
                       const float* __restrict__ acw, const float* __restrict__ acb,
                       const float* __restrict__ lastw, const float* __restrict__ lastb,
                       const float* __restrict__ l1w) {
    int i = blockIdx.x * blockDim.x + threadIdx.x;
    if (i < NN) g_deg[i] = 0;
    if (i < BB * HH) { g_gs0[i] = 0.f; g_gs1[i] = 0.f; }
    if (i < 2 * BB) { g_cnt[i] = 0.f; }
    if (i == 0) g_start[NN] = EE;
    // W^T -> bf16 for hops 1,2: g_wtb[(hop-1)][c][k] = bf16(W[hop][k][c])
    if (i < 2 * HH * HH) {
        int hop = i >> 14;
        int c = (i >> 7) & 127;
        int k = i & 127;
        g_wtb[i] = __float2bfloat16(l1w[(hop + 1) * HH * HH + k * HH + c]);
    }
    if (blockIdx.x == 0) {
        int t = threadIdx.x;  // 256
        if (t < HH) {
            float s = 0.f;
            for (int j = 0; j < HH; j++) s += spw[t * HH + j] * lastw[j];
            g_spvec[t] = s;
        }
        {
            float s = 0.f;
            for (int j = 0; j < HH; j++) s += acw[t * HH + j] * lastw[HH + j];
            if (t < HH) g_actop[t] = s; else g_acbot[t - HH] = s;
        }
        if (t < 32) {
            float s = 0.f;
            for (int j = t; j < HH; j += 32) s += spb[j] * lastw[j] + acb[j] * lastw[HH + j];
            for (int o = 16; o; o >>= 1) s += __shfl_down_sync(0xffffffffu, s, o);
            if (t == 0) g_c0 = s + lastb[0];
        }
    }
}

__global__ void k_hist(const int* __restrict__ row) {
    int e = blockIdx.x * blockDim.x + threadIdx.x;
    if (e < EE) atomicAdd(&g_deg[row[e]], 1);
}

// ---- scan ----
__global__ void k_scan1() {
    int t = threadIdx.x;                     // 256 threads, 512 nodes/block
    int n0 = blockIdx.x * 512;
    int s = 0;
    int i = n0 + t;
    if (i < NN) s += g_deg[i];
    if (i + 256 < n0 + 512 && i + 256 < NN) s += g_deg[i + 256];
    int lane = t & 31, warp = t >> 5;
    for (int o = 16; o; o >>= 1) s += __shfl_down_sync(0xffffffffu, s, o);
    __shared__ int ws[8];
    if (lane == 0) ws[warp] = s;
    __syncthreads();
    if (t == 0) {
        int tot = 0;
        #pragma unroll
        for (int w = 0; w < 8; w++) tot += ws[w];
        g_bsum[blockIdx.x] = tot;
    }
}

__global__ void k_scan3() {
    int t = threadIdx.x, blk = blockIdx.x;   // 256 threads
    __shared__ int ws[8], wo[8], sBoff;
    int lane = t & 31, warp = t >> 5;

    int bv = (t < blk) ? g_bsum[t] : 0;
    for (int o = 16; o; o >>= 1) bv += __shfl_down_sync(0xffffffffu, bv, o);
    if (lane == 0) ws[warp] = bv;
    __syncthreads();
    if (t == 0) {
        int tot = 0;
        #pragma unroll
        for (int w = 0; w < 8; w++) tot += ws[w];
        sBoff = tot;
    }
    __syncthreads();

    int i0 = blk * 512 + t * 2;
    int d0 = (i0 < NN) ? g_deg[i0] : 0;
    int d1 = (i0 + 1 < NN) ? g_deg[i0 + 1] : 0;
    int s = d0 + d1;
    int v = s;
    for (int o = 1; o < 32; o <<= 1) {
        int u = __shfl_up_sync(0xffffffffu, v, o);
        if (lane >= o) v += u;
    }
    if (lane == 31) ws[warp] = v;
    __syncthreads();
    if (t == 0) {
        int run = 0;
        #pragma unroll
        for (int w = 0; w < 8; w++) { wo[w] = run; run += ws[w]; }
    }
    __syncthreads();
    int ex = v - s + wo[warp] + sBoff;
    if (i0 < NN)     { g_start[i0] = ex;          g_cursor[i0] = ex; }
    if (i0 + 1 < NN) { g_start[i0 + 1] = ex + d0; g_cursor[i0 + 1] = ex + d0; }
}

__global__ void k_fill(const int* __restrict__ row, const int* __restrict__ col,
                       const float* __restrict__ ea) {
    int e = blockIdx.x * blockDim.x + threadIdx.x;
    if (e >= EE) return;
    int r = row[e];
    int idx = atomicAdd(&g_cursor[r], 1);
    g_ccol[idx] = col[e];
    g_cea[idx]  = ea[e];
}

// hop 0 fused (u==0): warp per node; lanes split edges for third term; emit bf16 u.
__global__ void k_hop0(const float* __restrict__ x,
                       const float* __restrict__ l3w, const float* __restrict__ l3b,
                       const float* __restrict__ l0w, const float* __restrict__ l0b,
                       const float* __restrict__ l1b,
                       const float* __restrict__ l2w, const float* __restrict__ l2b) {
    int warp = threadIdx.x >> 5, lane = threadIdx.x & 31;
    int n = blockIdx.x * 8 + warp;
    if (n >= NN) return;
    float w = l3w[0], b = l3b[0];
    int s = g_start[n], e = g_start[n + 1];
    float acc = 0.f;
    for (int t = s + lane; t < e; t += 32) acc += fmaxf(g_cea[t] * w + b, 0.f);
    for (int o = 16; o; o >>= 1) acc += __shfl_xor_sync(0xffffffffu, acc, o);
    float third = (e > s) ? acc / (float)(e - s) : 0.f;
    float xv = x[n];
    int h0 = lane * 4;
    float v0 = xv * l0w[h0]     + third * l2w[h0]     + l0b[h0]     + l1b[h0]     + l2b[h0];
    float v1 = xv * l0w[h0 + 1] + third * l2w[h0 + 1] + l0b[h0 + 1] + l1b[h0 + 1] + l2b[h0 + 1];
    float v2 = xv * l0w[h0 + 2] + third * l2w[h0 + 2] + l0b[h0 + 2] + l1b[h0 + 2] + l2b[h0 + 2];
    float v3 = xv * l0w[h0 + 3] + third * l2w[h0 + 3] + l0b[h0 + 3] + l1b[h0 + 3] + l2b[h0 + 3];
    __nv_bfloat162 lo = __floats2bfloat162_rn(fmaxf(v0, 0.f), fmaxf(v1, 0.f));
    __nv_bfloat162 hi = __floats2bfloat162_rn(fmaxf(v2, 0.f), fmaxf(v3, 0.f));
    uint2 pk;
    pk.x = *reinterpret_cast<unsigned*>(&lo);
    pk.y = *reinterpret_cast<unsigned*>(&hi);
    reinterpret_cast<uint2*>(g_ub)[(size_t)n * 32 + lane] = pk;
}

// edge aggregation: warp per node, CSR gather from bf16 rows, 4-edge unroll.
// Emits bf16 mean rows (mma A input) + fp32 third.
__global__ void k_gather(const float* __restrict__ l3w, const float* __restrict__ l3b) {
    int warp = threadIdx.x >> 5, lane = threadIdx.x & 31;
    int n = blockIdx.x * 8 + warp;
    if (n >= NN) return;
    const uint2* ub = reinterpret_cast<const uint2*>(g_ub);
    float w = l3w[0], b = l3b[0];
    int s = g_start[n], e = g_start[n + 1];
    float ax = 0.f, ay = 0.f, az = 0.f, aw = 0.f, tacc = 0.f;
    int t = s;
    for (; t + 3 < e; t += 4) {
        int c0 = g_ccol[t], c1 = g_ccol[t + 1], c2 = g_ccol[t + 2], c3 = g_ccol[t + 3];
        float a0 = g_cea[t], a1 = g_cea[t + 1], a2 = g_cea[t + 2], a3 = g_cea[t + 3];
        uint2 r0 = ub[(size_t)c0 * 32 + lane];
        uint2 r1 = ub[(size_t)c1 * 32 + lane];
        uint2 r2 = ub[(size_t)c2 * 32 + lane];
        uint2 r3 = ub[(size_t)c3 * 32 + lane];
        float2 p0 = __bfloat1622float2(*reinterpret_cast<__nv_bfloat162*>(&r0.x));
        float2 q0 = __bfloat1622float2(*reinterpret_cast<__nv_bfloat162*>(&r0.y));
        float2 p1 = __bfloat1622float2(*reinterpret_cast<__nv_bfloat162*>(&r1.x));
        float2 q1 = __bfloat1622float2(*reinterpret_cast<__nv_bfloat162*>(&r1.y));
        float2 p2 = __bfloat1622float2(*reinterpret_cast<__nv_bfloat162*>(&r2.x));
        float2 q2 = __bfloat1622float2(*reinterpret_cast<__nv_bfloat162*>(&r2.y));
        float2 p3 = __bfloat1622float2(*reinterpret_cast<__nv_bfloat162*>(&r3.x));
        float2 q3 = __bfloat1622float2(*reinterpret_cast<__nv_bfloat162*>(&r3.y));
        ax += a0 * p0.x + a1 * p1.x + a2 * p2.x + a3 * p3.x;
        ay += a0 * p0.y + a1 * p1.y + a2 * p2.y + a3 * p3.y;
        az += a0 * q0.x + a1 * q1.x + a2 * q2.x + a3 * q3.x;
        aw += a0 * q0.y + a1 * q1.y + a2 * q2.y + a3 * q3.y;
        tacc += fmaxf(a0 * w + b, 0.f) + fmaxf(a1 * w + b, 0.f)
              + fmaxf(a2 * w + b, 0.f) + fmaxf(a3 * w + b, 0.f);
    }
    for (; t < e; t++) {
        int c0 = g_ccol[t];
        float a0 = g_cea[t];
        uint2 r0 = ub[(size_t)c0 * 32 + lane];
        float2 p0 = __bfloat1622float2(*reinterpret_cast<__nv_bfloat162*>(&r0.x));
        float2 q0 = __bfloat1622float2(*reinterpret_cast<__nv_bfloat162*>(&r0.y));
        ax += a0 * p0.x; ay += a0 * p0.y; az += a0 * q0.x; aw += a0 * q0.y;
        tacc += fmaxf(a0 * w + b, 0.f);
    }
    float inv = (e > s) ? 1.f / (float)(e - s) : 0.f;
    __nv_bfloat162 lo = __floats2bfloat162_rn(ax * inv, ay * inv);
    __nv_bfloat162 hi = __floats2bfloat162_rn(az * inv, aw * inv);
    uint2 pk;
    pk.x = *reinterpret_cast<unsigned*>(&lo);
    pk.y = *reinterpret_cast<unsigned*>(&hi);
    g_meanb[(size_t)n * 32 + lane] = pk;
    if (lane == 0) g_third[n] = tacc * inv;
}

// bf16 tensor-core GEMM via mma.sync (base sm_103 ISA) + fused hop epilogue.
// CTA = 128 nodes x 128 cols, K=128. 8 warps; warp w owns rows m0=w*16.
// Always emits bf16 u into g_ub (safe: previous consumer ended at kernel boundary).
__global__ __launch_bounds__(256) void k_hmma(
    const float* __restrict__ x,
    const __nv_bfloat16* __restrict__ wtb,   // [128 c][128 k] bf16 row-major
    const float* __restrict__ l0w, const float* __restrict__ l2w,
    const float* __restrict__ b0, const float* __restrict__ b1,
    const float* __restrict__ b2) {
    extern __shared__ char smem[];
    uint32_t sbase = smem_u32(smem);
    int tid = threadIdx.x, lane = tid & 31, w = tid >> 5;
    int n0g = blockIdx.x * 128;

    // stage A (bf16 mean rows, 8 B per lane-step)
    for (int i = tid; i < 128 * 32; i += 256) {
        int row = i >> 5, u2 = i & 31;
        int n = n0g + row;
        uint2 v = (n < NN) ? g_meanb[(size_t)n * 32 + u2] : make_uint2(0u, 0u);
        *reinterpret_cast<uint2*>(smem + SH_A + row * (ASTB * 2) + u2 * 8) = v;
    }
    // stage B^T
    const uint2* wb = reinterpret_cast<const uint2*>(wtb);
    for (int i = tid; i < 128 * 32; i += 256) {
        int row = i >> 5, u2 = i & 31;
        *reinterpret_cast<uint2*>(smem + SH_B + row * (ASTB * 2) + u2 * 8) = wb[row * 32 + u2];
    }
    if (tid < 128) {
        reinterpret_cast<float*>(smem + SH_CB)[tid] = b0[tid] + b1[tid] + b2[tid];
        reinterpret_cast<float*>(smem + SH_C0)[tid] = l0w[tid];
        reinterpret_cast<float*>(smem + SH_C2)[tid] = l2w[tid];
    }
    __syncthreads();

    // ldmatrix lane addressing
    int lg = lane >> 3, li = lane & 7;
    int rowA = w * 16 + (lg & 1) * 8 + li;          // A rows for this warp
    uint32_t aBase = sbase + SH_A + rowA * (ASTB * 2) + ((lg >> 1) * 8) * 2;
    int rowBb = (lg >> 1) * 8 + li;                 // B row base within n-tile pair
    uint32_t bBase = sbase + SH_B + rowBb * (ASTB * 2) + ((lg & 1) * 8) * 2;

    float acc[16][4];
    #pragma unroll
    for (int t = 0; t < 16; t++)
        #pragma unroll
        for (int j = 0; j < 4; j++) acc[t][j] = 0.f;

    #pragma unroll 1
    for (int ks = 0; ks < 8; ks++) {
        uint32_t kb2 = ks * 32;   // kb*2 bytes
        uint32_t a0, a1, a2, a3;
        asm volatile("ldmatrix.sync.aligned.m8n8.x4.shared.b16 {%0,%1,%2,%3}, [%4];"
                     : "=r"(a0), "=r"(a1), "=r"(a2), "=r"(a3) : "r"(aBase + kb2));
        #pragma unroll
        for (int np = 0; np < 8; np++) {
            uint32_t r0, r1, r2, r3;
            asm volatile("ldmatrix.sync.aligned.m8n8.x4.shared.b16 {%0,%1,%2,%3}, [%4];"
                         : "=r"(r0), "=r"(r1), "=r"(r2), "=r"(r3)
                         : "r"(bBase + np * 16 * (ASTB * 2) + kb2));
            asm volatile(
                "mma.sync.aligned.m16n8k16.row.col.f32.bf16.bf16.f32 "
                "{%0,%1,%2,%3}, {%4,%5,%6,%7}, {%8,%9}, {%0,%1,%2,%3};"
                : "+f"(acc[2 * np][0]), "+f"(acc[2 * np][1]),
                  "+f"(acc[2 * np][2]), "+f"(acc[2 * np][3])
                : "r"(a0), "r"(a1), "r"(a2), "r"(a3), "r"(r0), "r"(r1));
            asm volatile(
                "mma.sync.aligned.m16n8k16.row.col.f32.bf16.bf16.f32 "
                "{%0,%1,%2,%3}, {%4,%5,%6,%7}, {%8,%9}, {%0,%1,%2,%3};"
                : "+f"(acc[2 * np + 1][0]), "+f"(acc[2 * np + 1][1]),
                  "+f"(acc[2 * np + 1][2]), "+f"(acc[2 * np + 1][3])
                : "r"(a0), "r"(a1), "r"(a2), "r"(a3), "r"(r2), "r"(r3));
        }
    }

    // epilogue: thread holds rows (m0 + lane/4) and (+8), cols 8t + (lane%4)*2, +1
    int q = lane & 3;
    int row0 = w * 16 + (lane >> 2), row1 = row0 + 8;
    int nA = n0g + row0, nB = n0g + row1;
    float xA = 0.f, tA = 0.f, xB = 0.f, tB = 0.f;
    if (nA < NN) { xA = x[nA]; tA = g_third[nA]; }
    if (nB < NN) { xB = x[nB]; tB = g_third[nB]; }
    const float* sCB = reinterpret_cast<const float*>(smem + SH_CB);
    const float* sC0 = reinterpret_cast<const float*>(smem + SH_C0);
    const float* sC2 = reinterpret_cast<const float*>(smem + SH_C2);

    #pragma unroll
    for (int t = 0; t < 16; t++) {
        int c = t * 8 + q * 2;
        float2 bb = *reinterpret_cast<const float2*>(&sCB[c]);
        float2 w0 = *reinterpret_cast<const float2*>(&sC0[c]);
        float2 w2 = *reinterpret_cast<const float2*>(&sC2[c]);
        float oA0 = fmaxf(xA * w0.x + tA * w2.x + bb.x + acc[t][0], 0.f);
        float oA1 = fmaxf(xA * w0.y + tA * w2.y + bb.y + acc[t][1], 0.f);
        float oB0 = fmaxf(xB * w0.x + tB * w2.x + bb.x + acc[t][2], 0.f);
        float oB1 = fmaxf(xB * w0.y + tB * w2.y + bb.y + acc[t][3], 0.f);
        if (nA < NN) g_ub[(size_t)nA * 64 + (c >> 1)] = __floats2bfloat162_rn(oA0, oA1);
        if (nB < NN) g_ub[(size_t)nB * 64 + (c >> 1)] = __floats2bfloat162_rn(oB0, oB1);
    }
}

// per-graph pooled sums (batch sorted -> register accumulate, flush on change)
// reads bf16 u
__global__ void k_pool(const float* __restrict__ x, const int* __restrict__ batch) {
    int h = threadIdx.x;               // 128
    int n0 = blockIdx.x * 128;
    if (n0 >= NN) return;
    int n1 = n0 + 128; if (n1 > NN) n1 = NN;
    const __nv_bfloat16* ubh = reinterpret_cast<const __nv_bfloat16*>(g_ub);
    int gcur = batch[n0];
    float a0 = 0.f, a1 = 0.f, c0 = 0.f, c1 = 0.f;
    for (int n = n0; n < n1; n++) {
        int g = batch[n];
        if (g != gcur) {
            atomicAdd(&g_gs0[gcur * HH + h], a0);
            atomicAdd(&g_gs1[gcur * HH + h], a1);
            if (h == 0) { atomicAdd(&g_cnt[gcur], c0); atomicAdd(&g_cnt[BB + gcur], c1); }
            a0 = a1 = c0 = c1 = 0.f;
            gcur = g;
        }
        float xv = x[n];
        float uv = __bfloat162float(ubh[(size_t)n * HH + h]);
        a0 += uv * (1.f - xv); a1 += uv * xv;
        c0 += 1.f - xv;        c1 += xv;
    }
    atomicAdd(&g_gs0[gcur * HH + h], a0);
    atomicAdd(&g_gs1[gcur * HH + h], a1);
    if (h == 0) { atomicAdd(&g_cnt[gcur], c0); atomicAdd(&g_cnt[BB + gcur], c1); }
}

// per-graph: hc0/hc1, folded attention vectors v0/v1 = att_w @ hc, and 10 scalars
__global__ void k_graph(const float* __restrict__ attw, const float* __restrict__ attb) {
    __shared__ float hc0[HH], hc1[HH], v0[2 * HH], v1[2 * HH];
    int g = blockIdx.x, t = threadIdx.x;  // 256 threads
    if (t < HH) {
        float c0 = g_cnt[g], c1 = g_cnt[BB + g];
        hc0[t] = (c0 > 0.f) ? g_gs0[g * HH + t] / c0 : 0.f;
        hc1[t] = (c1 > 0.f) ? g_gs1[g * HH + t] / c1 : 0.f;
    }
    __syncthreads();
    {
        float s0 = 0.f, s1 = 0.f;
        const float* wrow = attw + t * HH;
        for (int j = 0; j < HH; j++) { float w = wrow[j]; s0 += w * hc0[j]; s1 += w * hc1[j]; }
        v0[t] = s0; v1[t] = s1;
        if (t < HH) { g_v0t[g * HH + t] = s0; g_v1t[g * HH + t] = s1; }
    }
    __syncthreads();
    int warp = t >> 5, lane = t & 31;
    for (int id = warp; id < 10; id += 8) {
        const float* vec; const float* hc;
        switch (id) {
            case 0: vec = attb;     hc = hc0; break;  // s0
            case 1: vec = attb;     hc = hc1; break;  // s1
            case 2: vec = g_spvec;  hc = hc0; break;  // p0
            case 3: vec = g_spvec;  hc = hc1; break;  // p1
            case 4: vec = g_acbot;  hc = hc0; break;  // a0
            case 5: vec = g_acbot;  hc = hc1; break;  // a1
            case 6: vec = v0 + HH;  hc = hc0; break;  // d00
            case 7: vec = v0 + HH;  hc = hc1; break;  // d01
            case 8: vec = v1 + HH;  hc = hc0; break;  // d10
            default: vec = v1 + HH; hc = hc1; break;  // d11
        }
        float s = 0.f;
        for (int j = lane; j < HH; j += 32) s += vec[j] * hc[j];
        for (int o = 16; o; o >>= 1) s += __shfl_down_sync(0xffffffffu, s, o);
        if (lane == 0) g_scal[g * 10 + id] = s;
    }
}

// per-node head: 3 dots of length 128 + softmax over 2 + folded output (bf16 u)
__global__ void k_final(const float* __restrict__ x, const int* __restrict__ batch,
                        float* __restrict__ out) {
    int warp = threadIdx.x >> 5, lane = threadIdx.x & 31;
    int n = blockIdx.x * 8 + warp;
    if (n >= NN) return;
    int g = batch[n];
    uint2 upk = reinterpret_cast<const uint2*>(g_ub)[(size_t)n * 32 + lane];
    float2 ulo = __bfloat1622float2(*reinterpret_cast<__nv_bfloat162*>(&upk.x));
    float2 uhi = __bfloat1622float2(*reinterpret_cast<__nv_bfloat162*>(&upk.y));
    float4 uv = make_float4(ulo.x, ulo.y, uhi.x, uhi.y);
    float4 vA = *reinterpret_cast<const float4*>(&g_v0t[g * HH + lane * 4]);
    float4 vB = *reinterpret_cast<const float4*>(&g_v1t[g * HH + lane * 4]);
    float4 vC = *reinterpret_cast<const float4*>(&g_actop[lane * 4]);
    float da = uv.x * vA.x + uv.y * vA.y + uv.z * vA.z + uv.w * vA.w;
    float db = uv.x * vB.x + uv.y * vB.y + uv.z * vB.z + uv.w * vB.w;
    float dc = uv.x * vC.x + uv.y * vC.y + uv.z * vC.z + uv.w * vC.w;
    for (int o = 16; o; o >>= 1) {
        da += __shfl_down_sync(0xffffffffu, da, o);
        db += __shfl_down_sync(0xffffffffu, db, o);
        dc += __shfl_down_sync(0xffffffffu, dc, o);
    }
    if (lane == 0) {
        const float* sc = &g_scal[g * 10];
        bool xb = x[n] > 0.5f;
        float w0 = da + (xb ? sc[6] : sc[7]) + sc[0];
        float w1 = db + (xb ? sc[8] : sc[9]) + sc[1];
        float m = fmaxf(w0, w1);
        float e0 = __expf(w0 - m), e1 = __expf(w1 - m);
        float sw = e0 / (e0 + e1);
        out[n] = sw * sc[2] + (1.f - sw) * sc[3] + dc + (xb ? sc[4] : sc[5]) + g_c0;
    }
}

// ---------------- launch ----------------
extern "C" void kernel_launch(void* const* d_in, const int* in_sizes, int n_in,
                              void* d_out, int out_size) {
    int base = (n_in >= 21) ? 5 : 4;
    const float* x     = (const float*)d_in[0];
    const int*   ei    = (const int*)d_in[1];
    const float* ea    = (const float*)d_in[2];
    const int*   batch = (const int*)d_in[3];
    const float* l0w   = (const float*)d_in[base + 0];
    const float* l0b   = (const float*)d_in[base + 1];
    const float* l1w   = (const float*)d_in[base + 2];
    const float* l1b   = (const float*)d_in[base + 3];
    const float* l2w   = (const float*)d_in[base + 4];
    const float* l2b   = (const float*)d_in[base + 5];
    const float* l3w   = (const float*)d_in[base + 6];
    const float* l3b   = (const float*)d_in[base + 7];
    const float* attw  = (const float*)d_in[base + 8];
    const float* attb  = (const float*)d_in[base + 9];
    const float* spw   = (const float*)d_in[base + 10];
    const float* spb   = (const float*)d_in[base + 11];
    const float* acw   = (const float*)d_in[base + 12];
    const float* acb   = (const float*)d_in[base + 13];
    const float* lastw = (const float*)d_in[base + 14];
    const float* lastb = (const float*)d_in[base + 15];
    const int* row = ei;
    const int* col = ei + EE;
    float* out = (float*)d_out;

    static __nv_bfloat16* wtb_dev = nullptr;
    if (!wtb_dev) cudaGetSymbolAddress((void**)&wtb_dev, g_wtb);

    cudaFuncSetAttribute(k_hmma, cudaFuncAttributeMaxDynamicSharedMemorySize, SH_TOTAL);

    k_zero<<<(NN + 255) / 256, 256>>>(spw, spb, acw, acb, lastw, lastb, l1w);
    k_hist<<<(EE + 255) / 256, 256>>>(row);
    k_scan1<<<NB1, 256>>>();
    k_scan3<<<NB1, 256>>>();
    k_fill<<<(EE + 255) / 256, 256>>>(row, col, ea);

    // hop 0 (u == 0): fused third+update, bf16 out
    k_hop0<<<(NN + 7) / 8, 256>>>(x, l3w, l3b, l0w, l0b, l1b, l2w, l2b);

    // hops 1, 2: gather then tensor-core GEMM (bf16 u out)
    for (int i = 1; i < 3; i++) {
        k_gather<<<(NN + 7) / 8, 256>>>(l3w + i, l3b + i);
        k_hmma<<<(NN + 127) / 128, 256, SH_TOTAL>>>(
            x, wtb_dev + (i - 1) * HH * HH,
            l0w + i * HH, l2w + i * HH,
            l0b + i * HH, l1b + i * HH, l2b + i * HH);
    }

    k_pool<<<(NN + 127) / 128, 128>>>(x, batch);
    k_graph<<<BB, 256>>>(attw, attb);
    k_final<<<NN / 8, 256>>>(x, batch, out);
}

// round 12
// speedup vs baseline: 1.4890x; 1.0134x over previous
#include <cuda_runtime.h>
#include <cuda_bf16.h>
#include <cstdint>

#define NN 100000
#define EE 800000
#define HH 128
#define BB 64
#define NB1 196   // ceil(NN/512)

// ---------------- scratch (device globals: no runtime allocation) ----------------
__device__ __nv_bfloat162 g_ub[(size_t)NN * 64]; // bf16 u (gather input + head path)
__device__ uint2 g_meanb[(size_t)NN * 32];       // bf16 seg-mean rows (mma A input)
__device__ __nv_bfloat16 g_wtb[2 * HH * HH];     // bf16 W^T for hops 1,2  [c][k]
__device__ float g_third[NN];                    // seg_mean(ee) per node (per hop)
__device__ int   g_deg[NN];
__device__ int   g_start[NN + 1];
__device__ int   g_cursor[NN];
__device__ int   g_bsum[NB1 + 4];
__device__ int2  g_edge[EE];                     // packed (col, ea-bits) per CSR slot
__device__ float g_gs0[BB * HH], g_gs1[BB * HH];
__device__ float g_cnt[2 * BB];
__device__ float g_v0t[BB * HH], g_v1t[BB * HH];
__device__ float g_scal[BB * 10];                // s0,s1,p0,p1,a0,a1,d00,d01,d10,d11
__device__ float g_spvec[HH], g_actop[HH], g_acbot[HH];
__device__ float g_c0;

__device__ __forceinline__ uint32_t smem_u32(const void* p) {
    uint32_t a;
    asm("{ .reg .u64 t; cvta.to.shared.u64 t, %1; cvt.u32.u64 %0, t; }" : "=r"(a) : "l"(p));
    return a;
}

// smem layout for k_hmma (bf16, rows padded to 136 elems = 272 B)
#define ASTB 136
#define SH_A 0
#define SH_B (128 * ASTB * 2)            // 34816
#define SH_CB (2 * 128 * ASTB * 2)       // 69632
#define SH_C0 (SH_CB + 512)
#define SH_C2 (SH_C0 + 512)
#define SH_TOTAL (SH_C2 + 512)           // 71168

// ---------------- zero + folded final-layer vectors + W^T bf16 (merged) ----------------
__global__ void k_zero(const float* __restrict__ spw, const float* __restrict__ spb,
                       const float* __restrict__ acw, const float* __restrict__ acb,
                       const float* __restrict__ lastw, const float* __restrict__ lastb,
                       const float* __restrict__ l1w) {
    int i = blockIdx.x * blockDim.x + threadIdx.x;
    if (i < NN) g_deg[i] = 0;
    if (i < BB * HH) { g_gs0[i] = 0.f; g_gs1[i] = 0.f; }
    if (i < 2 * BB) { g_cnt[i] = 0.f; }
    if (i == 0) g_start[NN] = EE;
    // W^T -> bf16 for hops 1,2: g_wtb[(hop-1)][c][k] = bf16(W[hop][k][c])
    if (i < 2 * HH * HH) {
        int hop = i >> 14;
        int c = (i >> 7) & 127;
        int k = i & 127;
        g_wtb[i] = __float2bfloat16(l1w[(hop + 1) * HH * HH + k * HH + c]);
    }
    if (blockIdx.x == 0) {
        int t = threadIdx.x;  // 256
        if (t < HH) {
            float s = 0.f;
            for (int j = 0; j < HH; j++) s += spw[t * HH + j] * lastw[j];
            g_spvec[t] = s;
        }
        {
            float s = 0.f;
            for (int j = 0; j < HH; j++) s += acw[t * HH + j] * lastw[HH + j];
            if (t < HH) g_actop[t] = s; else g_acbot[t - HH] = s;
        }
        if (t < 32) {
            float s = 0.f;
            for (int j = t; j < HH; j += 32) s += spb[j] * lastw[j] + acb[j] * lastw[HH + j];
            for (int o = 16; o; o >>= 1) s += __shfl_down_sync(0xffffffffu, s, o);
            if (t == 0) g_c0 = s + lastb[0];
        }
    }
}

__global__ void k_hist(const int* __restrict__ row) {
    int e = blockIdx.x * blockDim.x + threadIdx.x;
    if (e < EE) atomicAdd(&g_deg[row[e]], 1);
}

// ---- scan ----
__global__ void k_scan1() {
    int t = threadIdx.x;                     // 256 threads, 512 nodes/block
    int n0 = blockIdx.x * 512;
    int s = 0;
    int i = n0 + t;
    if (i < NN) s += g_deg[i];
    if (i + 256 < n0 + 512 && i + 256 < NN) s += g_deg[i + 256];
    int lane = t & 31, warp = t >> 5;
    for (int o = 16; o; o >>= 1) s += __shfl_down_sync(0xffffffffu, s, o);
    __shared__ int ws[8];
    if (lane == 0) ws[warp] = s;
    __syncthreads();
    if (t == 0) {
        int tot = 0;
        #pragma unroll
        for (int w = 0; w < 8; w++) tot += ws[w];
        g_bsum[blockIdx.x] = tot;
    }
}

__global__ void k_scan3() {
    int t = threadIdx.x, blk = blockIdx.x;   // 256 threads
    __shared__ int ws[8], wo[8], sBoff;
    int lane = t & 31, warp = t >> 5;

    int bv = (t < blk) ? g_bsum[t] : 0;
    for (int o = 16; o; o >>= 1) bv += __shfl_down_sync(0xffffffffu, bv, o);
    if (lane == 0) ws[warp] = bv;
    __syncthreads();
    if (t == 0) {
        int tot = 0;
        #pragma unroll
        for (int w = 0; w < 8; w++) tot += ws[w];
        sBoff = tot;
    }
    __syncthreads();

    int i0 = blk * 512 + t * 2;
    int d0 = (i0 < NN) ? g_deg[i0] : 0;
    int d1 = (i0 + 1 < NN) ? g_deg[i0 + 1] : 0;
    int s = d0 + d1;
    int v = s;
    for (int o = 1; o < 32; o <<= 1) {
        int u = __shfl_up_sync(0xffffffffu, v, o);
        if (lane >= o) v += u;
    }
    if (lane == 31) ws[warp] = v;
    __syncthreads();
    if (t == 0) {
        int run = 0;
        #pragma unroll
        for (int w = 0; w < 8; w++) { wo[w] = run; run += ws[w]; }
    }
    __syncthreads();
    int ex = v - s + wo[warp] + sBoff;
    if (i0 < NN)     { g_start[i0] = ex;          g_cursor[i0] = ex; }
    if (i0 + 1 < NN) { g_start[i0 + 1] = ex + d0; g_cursor[i0 + 1] = ex + d0; }
}

__global__ void k_fill(const int* __restrict__ row, const int* __restrict__ col,
                       const float* __restrict__ ea) {
    int e = blockIdx.x * blockDim.x + threadIdx.x;
    if (e >= EE) return;
    int r = row[e];
    int idx = atomicAdd(&g_cursor[r], 1);
    int2 pk;
    pk.x = col[e];
    pk.y = __float_as_int(ea[e]);
    g_edge[idx] = pk;
}

// hop 0 fused (u==0): warp per node; lanes split edges for third term; emit bf16 u.
__global__ void k_hop0(const float* __restrict__ x,
                       const float* __restrict__ l3w, const float* __restrict__ l3b,
                       const float* __restrict__ l0w, const float* __restrict__ l0b,
                       const float* __restrict__ l1b,
                       const float* __restrict__ l2w, const float* __restrict__ l2b) {
    int warp = threadIdx.x >> 5, lane = threadIdx.x & 31;
    int n = blockIdx.x * 8 + warp;
    if (n >= NN) return;
    float w = l3w[0], b = l3b[0];
    int s = g_start[n], e = g_start[n + 1];
    float acc = 0.f;
    for (int t = s + lane; t < e; t += 32)
        acc += fmaxf(__int_as_float(g_edge[t].y) * w + b, 0.f);
    for (int o = 16; o; o >>= 1) acc += __shfl_xor_sync(0xffffffffu, acc, o);
    float third = (e > s) ? acc / (float)(e - s) : 0.f;
    float xv = x[n];
    int h0 = lane * 4;
    float v0 = xv * l0w[h0]     + third * l2w[h0]     + l0b[h0]     + l1b[h0]     + l2b[h0];
    float v1 = xv * l0w[h0 + 1] + third * l2w[h0 + 1] + l0b[h0 + 1] + l1b[h0 + 1] + l2b[h0 + 1];
    float v2 = xv * l0w[h0 + 2] + third * l2w[h0 + 2] + l0b[h0 + 2] + l1b[h0 + 2] + l2b[h0 + 2];
    float v3 = xv * l0w[h0 + 3] + third * l2w[h0 + 3] + l0b[h0 + 3] + l1b[h0 + 3] + l2b[h0 + 3];
    __nv_bfloat162 lo = __floats2bfloat162_rn(fmaxf(v0, 0.f), fmaxf(v1, 0.f));
    __nv_bfloat162 hi = __floats2bfloat162_rn(fmaxf(v2, 0.f), fmaxf(v3, 0.f));
    uint2 pk;
    pk.x = *reinterpret_cast<unsigned*>(&lo);
    pk.y = *reinterpret_cast<unsigned*>(&hi);
    reinterpret_cast<uint2*>(g_ub)[(size_t)n * 32 + lane] = pk;
}

// edge aggregation: warp per node, CSR gather from bf16 rows, 4-edge unroll.
// Packed edge stream (1x8B load/edge). Emits bf16 mean rows + fp32 third.
__global__ void k_gather(const float* __restrict__ l3w, const float* __restrict__ l3b) {
    int warp = threadIdx.x >> 5, lane = threadIdx.x & 31;
    int n = blockIdx.x * 8 + warp;
    if (n >= NN) return;
    const uint2* ub = reinterpret_cast<const uint2*>(g_ub);
    float w = l3w[0], b = l3b[0];
    int s = g_start[n], e = g_start[n + 1];
    float ax = 0.f, ay = 0.f, az = 0.f, aw = 0.f, tacc = 0.f;
    int t = s;
    for (; t + 3 < e; t += 4) {
        int2 e0 = g_edge[t],     e1 = g_edge[t + 1];
        int2 e2 = g_edge[t + 2], e3 = g_edge[t + 3];
        float a0 = __int_as_float(e0.y), a1 = __int_as_float(e1.y);
        float a2 = __int_as_float(e2.y), a3 = __int_as_float(e3.y);
        uint2 r0 = ub[(size_t)e0.x * 32 + lane];
        uint2 r1 = ub[(size_t)e1.x * 32 + lane];
        uint2 r2 = ub[(size_t)e2.x * 32 + lane];
        uint2 r3 = ub[(size_t)e3.x * 32 + lane];
        float2 p0 = __bfloat1622float2(*reinterpret_cast<__nv_bfloat162*>(&r0.x));
        float2 q0 = __bfloat1622float2(*reinterpret_cast<__nv_bfloat162*>(&r0.y));
        float2 p1 = __bfloat1622float2(*reinterpret_cast<__nv_bfloat162*>(&r1.x));
        float2 q1 = __bfloat1622float2(*reinterpret_cast<__nv_bfloat162*>(&r1.y));
        float2 p2 = __bfloat1622float2(*reinterpret_cast<__nv_bfloat162*>(&r2.x));
        float2 q2 = __bfloat1622float2(*reinterpret_cast<__nv_bfloat162*>(&r2.y));
        float2 p3 = __bfloat1622float2(*reinterpret_cast<__nv_bfloat162*>(&r3.x));
        float2 q3 = __bfloat1622float2(*reinterpret_cast<__nv_bfloat162*>(&r3.y));
        ax += a0 * p0.x + a1 * p1.x + a2 * p2.x + a3 * p3.x;
        ay += a0 * p0.y + a1 * p1.y + a2 * p2.y + a3 * p3.y;
        az += a0 * q0.x + a1 * q1.x + a2 * q2.x + a3 * q3.x;
        aw += a0 * q0.y + a1 * q1.y + a2 * q2.y + a3 * q3.y;
        tacc += fmaxf(a0 * w + b, 0.f) + fmaxf(a1 * w + b, 0.f)
              + fmaxf(a2 * w + b, 0.f) + fmaxf(a3 * w + b, 0.f);
    }
    for (; t < e; t++) {
        int2 e0 = g_edge[t];
        float a0 = __int_as_float(e0.y);
        uint2 r0 = ub[(size_t)e0.x * 32 + lane];
        float2 p0 = __bfloat1622float2(*reinterpret_cast<__nv_bfloat162*>(&r0.x));
        float2 q0 = __bfloat1622float2(*reinterpret_cast<__nv_bfloat162*>(&r0.y));
        ax += a0 * p0.x; ay += a0 * p0.y; az += a0 * q0.x; aw += a0 * q0.y;
        tacc += fmaxf(a0 * w + b, 0.f);
    }
    float inv = (e > s) ? 1.f / (float)(e - s) : 0.f;
    __nv_bfloat162 lo = __floats2bfloat162_rn(ax * inv, ay * inv);
    __nv_bfloat162 hi = __floats2bfloat162_rn(az * inv, aw * inv);
    uint2 pk;
    pk.x = *reinterpret_cast<unsigned*>(&lo);
    pk.y = *reinterpret_cast<unsigned*>(&hi);
    g_meanb[(size_t)n * 32 + lane] = pk;
    if (lane == 0) g_third[n] = tacc * inv;
}

// bf16 tensor-core GEMM via mma.sync (base sm_103 ISA) + fused hop epilogue.
// CTA = 128 nodes x 128 cols, K=128. 8 warps; warp w owns rows m0=w*16.
// Always emits bf16 u into g_ub (safe: previous consumer ended at kernel boundary).
__global__ __launch_bounds__(256) void k_hmma(
    const float* __restrict__ x,
    const __nv_bfloat16* __restrict__ wtb,   // [128 c][128 k] bf16 row-major
    const float* __restrict__ l0w, const float* __restrict__ l2w,
    const float* __restrict__ b0, const float* __restrict__ b1,
    const float* __restrict__ b2) {
    extern __shared__ char smem[];
    uint32_t sbase = smem_u32(smem);
    int tid = threadIdx.x, lane = tid & 31, w = tid >> 5;
    int n0g = blockIdx.x * 128;

    // stage A (bf16 mean rows, 8 B per lane-step)
    for (int i = tid; i < 128 * 32; i += 256) {
        int row = i >> 5, u2 = i & 31;
        int n = n0g + row;
        uint2 v = (n < NN) ? g_meanb[(size_t)n * 32 + u2] : make_uint2(0u, 0u);
        *reinterpret_cast<uint2*>(smem + SH_A + row * (ASTB * 2) + u2 * 8) = v;
    }
    // stage B^T
    const uint2* wb = reinterpret_cast<const uint2*>(wtb);
    for (int i = tid; i < 128 * 32; i += 256) {
        int row = i >> 5, u2 = i & 31;
        *reinterpret_cast<uint2*>(smem + SH_B + row * (ASTB * 2) + u2 * 8) = wb[row * 32 + u2];
    }
    if (tid < 128) {
        reinterpret_cast<float*>(smem + SH_CB)[tid] = b0[tid] + b1[tid] + b2[tid];
        reinterpret_cast<float*>(smem + SH_C0)[tid] = l0w[tid];
        reinterpret_cast<float*>(smem + SH_C2)[tid] = l2w[tid];
    }
    __syncthreads();

    // ldmatrix lane addressing
    int lg = lane >> 3, li = lane & 7;
    int rowA = w * 16 + (lg & 1) * 8 + li;          // A rows for this warp
    uint32_t aBase = sbase + SH_A + rowA * (ASTB * 2) + ((lg >> 1) * 8) * 2;
    int rowBb = (lg >> 1) * 8 + li;                 // B row base within n-tile pair
    uint32_t bBase = sbase + SH_B + rowBb * (ASTB * 2) + ((lg & 1) * 8) * 2;

    float acc[16][4];
    #pragma unroll
    for (int t = 0; t < 16; t++)
        #pragma unroll
        for (int j = 0; j < 4; j++) acc[t][j] = 0.f;

    #pragma unroll 1
    for (int ks = 0; ks < 8; ks++) {
        uint32_t kb2 = ks * 32;   // kb*2 bytes
        uint32_t a0, a1, a2, a3;
        asm volatile("ldmatrix.sync.aligned.m8n8.x4.shared.b16 {%0,%1,%2,%3}, [%4];"
                     : "=r"(a0), "=r"(a1), "=r"(a2), "=r"(a3) : "r"(aBase + kb2));
        #pragma unroll
        for (int np = 0; np < 8; np++) {
            uint32_t r0, r1, r2, r3;
            asm volatile("ldmatrix.sync.aligned.m8n8.x4.shared.b16 {%0,%1,%2,%3}, [%4];"
                         : "=r"(r0), "=r"(r1), "=r"(r2), "=r"(r3)
                         : "r"(bBase + np * 16 * (ASTB * 2) + kb2));
            asm volatile(
                "mma.sync.aligned.m16n8k16.row.col.f32.bf16.bf16.f32 "
                "{%0,%1,%2,%3}, {%4,%5,%6,%7}, {%8,%9}, {%0,%1,%2,%3};"
                : "+f"(acc[2 * np][0]), "+f"(acc[2 * np][1]),
                  "+f"(acc[2 * np][2]), "+f"(acc[2 * np][3])
                : "r"(a0), "r"(a1), "r"(a2), "r"(a3), "r"(r0), "r"(r1));
            asm volatile(
                "mma.sync.aligned.m16n8k16.row.col.f32.bf16.bf16.f32 "
                "{%0,%1,%2,%3}, {%4,%5,%6,%7}, {%8,%9}, {%0,%1,%2,%3};"
                : "+f"(acc[2 * np + 1][0]), "+f"(acc[2 * np + 1][1]),
                  "+f"(acc[2 * np + 1][2]), "+f"(acc[2 * np + 1][3])
                : "r"(a0), "r"(a1), "r"(a2), "r"(a3), "r"(r2), "r"(r3));
        }
    }

    // epilogue: thread holds rows (m0 + lane/4) and (+8), cols 8t + (lane%4)*2, +1
    int q = lane & 3;
    int row0 = w * 16 + (lane >> 2), row1 = row0 + 8;
    int nA = n0g + row0, nB = n0g + row1;
    float xA = 0.f, tA = 0.f, xB = 0.f, tB = 0.f;
    if (nA < NN) { xA = x[nA]; tA = g_third[nA]; }
    if (nB < NN) { xB = x[nB]; tB = g_third[nB]; }
    const float* sCB = reinterpret_cast<const float*>(smem + SH_CB);
    const float* sC0 = reinterpret_cast<const float*>(smem + SH_C0);
    const float* sC2 = reinterpret_cast<const float*>(smem + SH_C2);

    #pragma unroll
    for (int t = 0; t < 16; t++) {
        int c = t * 8 + q * 2;
        float2 bb = *reinterpret_cast<const float2*>(&sCB[c]);
        float2 w0 = *reinterpret_cast<const float2*>(&sC0[c]);
        float2 w2 = *reinterpret_cast<const float2*>(&sC2[c]);
        float oA0 = fmaxf(xA * w0.x + tA * w2.x + bb.x + acc[t][0], 0.f);
        float oA1 = fmaxf(xA * w0.y + tA * w2.y + bb.y + acc[t][1], 0.f);
        float oB0 = fmaxf(xB * w0.x + tB * w2.x + bb.x + acc[t][2], 0.f);
        float oB1 = fmaxf(xB * w0.y + tB * w2.y + bb.y + acc[t][3], 0.f);
        if (nA < NN) g_ub[(size_t)nA * 64 + (c >> 1)] = __floats2bfloat162_rn(oA0, oA1);
        if (nB < NN) g_ub[(size_t)nB * 64 + (c >> 1)] = __floats2bfloat162_rn(oB0, oB1);
    }
}

// per-graph pooled sums (batch sorted -> register accumulate, flush on change)
// reads bf16 u
__global__ void k_pool(const float* __restrict__ x, const int* __restrict__ batch) {
    int h = threadIdx.x;               // 128
    int n0 = blockIdx.x * 128;
    if (n0 >= NN) return;
    int n1 = n0 + 128; if (n1 > NN) n1 = NN;
    const __nv_bfloat16* ubh = reinterpret_cast<const __nv_bfloat16*>(g_ub);
    int gcur = batch[n0];
    float a0 = 0.f, a1 = 0.f, c0 = 0.f, c1 = 0.f;
    for (int n = n0; n < n1; n++) {
        int g = batch[n];
        if (g != gcur) {
            atomicAdd(&g_gs0[gcur * HH + h], a0);
            atomicAdd(&g_gs1[gcur * HH + h], a1);
            if (h == 0) { atomicAdd(&g_cnt[gcur], c0); atomicAdd(&g_cnt[BB + gcur], c1); }
            a0 = a1 = c0 = c1 = 0.f;
            gcur = g;
        }
        float xv = x[n];
        float uv = __bfloat162float(ubh[(size_t)n * HH + h]);
        a0 += uv * (1.f - xv); a1 += uv * xv;
        c0 += 1.f - xv;        c1 += xv;
    }
    atomicAdd(&g_gs0[gcur * HH + h], a0);
    atomicAdd(&g_gs1[gcur * HH + h], a1);
    if (h == 0) { atomicAdd(&g_cnt[gcur], c0); atomicAdd(&g_cnt[BB + gcur], c1); }
}

// per-graph: hc0/hc1, folded attention vectors v0/v1 = att_w @ hc, and 10 scalars
__global__ void k_graph(const float* __restrict__ attw, const float* __restrict__ attb) {
    __shared__ float hc0[HH], hc1[HH], v0[2 * HH], v1[2 * HH];
    int g = blockIdx.x, t = threadIdx.x;  // 256 threads
    if (t < HH) {
        float c0 = g_cnt[g], c1 = g_cnt[BB + g];
        hc0[t] = (c0 > 0.f) ? g_gs0[g * HH + t] / c0 : 0.f;
        hc1[t] = (c1 > 0.f) ? g_gs1[g * HH + t] / c1 : 0.f;
    }
    __syncthreads();
    {
        float s0 = 0.f, s1 = 0.f;
        const float* wrow = attw + t * HH;
        for (int j = 0; j < HH; j++) { float w = wrow[j]; s0 += w * hc0[j]; s1 += w * hc1[j]; }
        v0[t] = s0; v1[t] = s1;
        if (t < HH) { g_v0t[g * HH + t] = s0; g_v1t[g * HH + t] = s1; }
    }
    __syncthreads();
    int warp = t >> 5, lane = t & 31;
    for (int id = warp; id < 10; id += 8) {
        const float* vec; const float* hc;
        switch (id) {
            case 0: vec = attb;     hc = hc0; break;  // s0
            case 1: vec = attb;     hc = hc1; break;  // s1
            case 2: vec = g_spvec;  hc = hc0; break;  // p0
            case 3: vec = g_spvec;  hc = hc1; break;  // p1
            case 4: vec = g_acbot;  hc = hc0; break;  // a0
            case 5: vec = g_acbot;  hc = hc1; break;  // a1
            case 6: vec = v0 + HH;  hc = hc0; break;  // d00
            case 7: vec = v0 + HH;  hc = hc1; break;  // d01
            case 8: vec = v1 + HH;  hc = hc0; break;  // d10
            default: vec = v1 + HH; hc = hc1; break;  // d11
        }
        float s = 0.f;
        for (int j = lane; j < HH; j += 32) s += vec[j] * hc[j];
        for (int o = 16; o; o >>= 1) s += __shfl_down_sync(0xffffffffu, s, o);
        if (lane == 0) g_scal[g * 10 + id] = s;
    }
}

// per-node head: 3 dots of length 128 + softmax over 2 + folded output (bf16 u)
__global__ void k_final(const float* __restrict__ x, const int* __restrict__ batch,
                        float* __restrict__ out) {
    int warp = threadIdx.x >> 5, lane = threadIdx.x & 31;
    int n = blockIdx.x * 8 + warp;
    if (n >= NN) return;
    int g = batch[n];
    uint2 upk = reinterpret_cast<const uint2*>(g_ub)[(size_t)n * 32 + lane];
    float2 ulo = __bfloat1622float2(*reinterpret_cast<__nv_bfloat162*>(&upk.x));
    float2 uhi = __bfloat1622float2(*reinterpret_cast<__nv_bfloat162*>(&upk.y));
    float4 uv = make_float4(ulo.x, ulo.y, uhi.x, uhi.y);
    float4 vA = *reinterpret_cast<const float4*>(&g_v0t[g * HH + lane * 4]);
    float4 vB = *reinterpret_cast<const float4*>(&g_v1t[g * HH + lane * 4]);
    float4 vC = *reinterpret_cast<const float4*>(&g_actop[lane * 4]);
    float da = uv.x * vA.x + uv.y * vA.y + uv.z * vA.z + uv.w * vA.w;
    float db = uv.x * vB.x + uv.y * vB.y + uv.z * vB.z + uv.w * vB.w;
    float dc = uv.x * vC.x + uv.y * vC.y + uv.z * vC.z + uv.w * vC.w;
    for (int o = 16; o; o >>= 1) {
        da += __shfl_down_sync(0xffffffffu, da, o);
        db += __shfl_down_sync(0xffffffffu, db, o);
        dc += __shfl_down_sync(0xffffffffu, dc, o);
    }
    if (lane == 0) {
        const float* sc = &g_scal[g * 10];
        bool xb = x[n] > 0.5f;
        float w0 = da + (xb ? sc[6] : sc[7]) + sc[0];
        float w1 = db + (xb ? sc[8] : sc[9]) + sc[1];
        float m = fmaxf(w0, w1);
        float e0 = __expf(w0 - m), e1 = __expf(w1 - m);
        float sw = e0 / (e0 + e1);
        out[n] = sw * sc[2] + (1.f - sw) * sc[3] + dc + (xb ? sc[4] : sc[5]) + g_c0;
    }
}

// ---------------- launch ----------------
extern "C" void kernel_launch(void* const* d_in, const int* in_sizes, int n_in,
                              void* d_out, int out_size) {
    int base = (n_in >= 21) ? 5 : 4;
    const float* x     = (const float*)d_in[0];
    const int*   ei    = (const int*)d_in[1];
    const float* ea    = (const float*)d_in[2];
    const int*   batch = (const int*)d_in[3];
    const float* l0w   = (const float*)d_in[base + 0];
    const float* l0b   = (const float*)d_in[base + 1];
    const float* l1w   = (const float*)d_in[base + 2];
    const float* l1b   = (const float*)d_in[base + 3];
    const float* l2w   = (const float*)d_in[base + 4];
    const float* l2b   = (const float*)d_in[base + 5];
    const float* l3w   = (const float*)d_in[base + 6];
    const float* l3b   = (const float*)d_in[base + 7];
    const float* attw  = (const float*)d_in[base + 8];
    const float* attb  = (const float*)d_in[base + 9];
    const float* spw   = (const float*)d_in[base + 10];
    const float* spb   = (const float*)d_in[base + 11];
    const float* acw   = (const float*)d_in[base + 12];
    const float* acb   = (const float*)d_in[base + 13];
    const float* lastw = (const float*)d_in[base + 14];
    const float* lastb = (const float*)d_in[base + 15];
    const int* row = ei;
    const int* col = ei + EE;
    float* out = (float*)d_out;

    static __nv_bfloat16* wtb_dev = nullptr;
    if (!wtb_dev) cudaGetSymbolAddress((void**)&wtb_dev, g_wtb);

    cudaFuncSetAttribute(k_hmma, cudaFuncAttributeMaxDynamicSharedMemorySize, SH_TOTAL);

    k_zero<<<(NN + 255) / 256, 256>>>(spw, spb, acw, acb, lastw, lastb, l1w);
    k_hist<<<(EE + 255) / 256, 256>>>(row);
    k_scan1<<<NB1, 256>>>();
    k_scan3<<<NB1, 256>>>();
    k_fill<<<(EE + 255) / 256, 256>>>(row, col, ea);

    // hop 0 (u == 0): fused third+update, bf16 out
    k_hop0<<<(NN + 7) / 8, 256>>>(x, l3w, l3b, l0w, l0b, l1b, l2w, l2b);

    // hops 1, 2: gather then tensor-core GEMM (bf16 u out)
    for (int i = 1; i < 3; i++) {
        k_gather<<<(NN + 7) / 8, 256>>>(l3w + i, l3b + i);
        k_hmma<<<(NN + 127) / 128, 256, SH_TOTAL>>>(
            x, wtb_dev + (i - 1) * HH * HH,
            l0w + i * HH, l2w + i * HH,
            l0b + i * HH, l1b + i * HH, l2b + i * HH);
    }

    k_pool<<<(NN + 127) / 128, 128>>>(x, batch);
    k_graph<<<BB, 256>>>(attw, attb);
    k_final<<<NN / 8, 256>>>(x, batch, out);
}

// round 14
// speedup vs baseline: 1.5201x; 1.0209x over previous
#include <cuda_runtime.h>
#include <cuda_bf16.h>
#include <cstdint>

#define NN 100000
#define EE 800000
#define HH 128
#define BB 64
#define NB1 196   // ceil(NN/512)

// ---------------- scratch (device globals: no runtime allocation) ----------------
__device__ __nv_bfloat162 g_ub[(size_t)NN * 64]; // bf16 u (gather input + head path)
__device__ uint2 g_meanb[(size_t)NN * 32];       // bf16 seg-mean rows (mma A input)
__device__ __nv_bfloat16 g_wtb[2 * HH * HH];     // bf16 W^T for hops 1,2  [c][k]
__device__ float g_third[NN];                    // seg_mean(ee) per node (per hop)
__device__ int   g_deg[NN];
__device__ int   g_start[NN + 1];
__device__ int   g_cursor[NN];
__device__ int   g_bsum[NB1 + 4];
__device__ int2  g_edge[EE];                     // packed (col, ea-bits) per CSR slot
__device__ float g_gs0[BB * HH], g_gs1[BB * HH];
__device__ float g_cnt[2 * BB];
__device__ float g_v0t[BB * HH], g_v1t[BB * HH];
__device__ float g_scal[BB * 10];                // s0,s1,p0,p1,a0,a1,d00,d01,d10,d11
__device__ float g_spvec[HH], g_actop[HH], g_acbot[HH];
__device__ float g_c0;

__device__ __forceinline__ uint32_t smem_u32(const void* p) {
    uint32_t a;
    asm("{ .reg .u64 t; cvta.to.shared.u64 t, %1; cvt.u32.u64 %0, t; }" : "=r"(a) : "l"(p));
    return a;
}

// smem layout for k_hmma (bf16, rows padded to 136 elems = 272 B)
#define ASTB 136
#define SH_A 0
#define SH_B (128 * ASTB * 2)            // 34816
#define SH_CB (2 * 128 * ASTB * 2)       // 69632
#define SH_C0 (SH_CB + 512)
#define SH_C2 (SH_C0 + 512)
#define SH_TOTAL (SH_C2 + 512)           // 71168

// ---------------- zero + folded final-layer vectors + W^T bf16 (merged) ----------------
__global__ void k_zero(const float* __restrict__ spw, const float* __restrict__ spb,
                       const float* __restrict__ acw, const float* __restrict__ acb,
                       const float* __restrict__ lastw, const float* __restrict__ lastb,
                       const float* __restrict__ l1w) {
    int i = blockIdx.x * blockDim.x + threadIdx.x;
    if (i < NN) g_deg[i] = 0;
    if (i < BB * HH) { g_gs0[i] = 0.f; g_gs1[i] = 0.f; }
    if (i < 2 * BB) { g_cnt[i] = 0.f; }
    if (i == 0) g_start[NN] = EE;
    // W^T -> bf16 for hops 1,2: g_wtb[(hop-1)][c][k] = bf16(W[hop][k][c])
    if (i < 2 * HH * HH) {
        int hop = i >> 14;
        int c = (i >> 7) & 127;
        int k = i & 127;
        g_wtb[i] = __float2bfloat16(l1w[(hop + 1) * HH * HH + k * HH + c]);
    }
    if (blockIdx.x == 0) {
        int t = threadIdx.x;  // 256
        if (t < HH) {
            float s = 0.f;
            for (int j = 0; j < HH; j++) s += spw[t * HH + j] * lastw[j];
            g_spvec[t] = s;
        }
        {
            float s = 0.f;
            for (int j = 0; j < HH; j++) s += acw[t * HH + j] * lastw[HH + j];
            if (t < HH) g_actop[t] = s; else g_acbot[t - HH] = s;
        }
        if (t < 32) {
            float s = 0.f;
            for (int j = t; j < HH; j += 32) s += spb[j] * lastw[j] + acb[j] * lastw[HH + j];
            for (int o = 16; o; o >>= 1) s += __shfl_down_sync(0xffffffffu, s, o);
            if (t == 0) g_c0 = s + lastb[0];
        }
    }
}

__global__ void k_hist(const int* __restrict__ row) {
    int e = blockIdx.x * blockDim.x + threadIdx.x;
    if (e < EE) atomicAdd(&g_deg[row[e]], 1);
}

// ---- scan ----
__global__ void k_scan1() {
    int t = threadIdx.x;                     // 256 threads, 512 nodes/block
    int n0 = blockIdx.x * 512;
    int s = 0;
    int i = n0 + t;
    if (i < NN) s += g_deg[i];
    if (i + 256 < n0 + 512 && i + 256 < NN) s += g_deg[i + 256];
    int lane = t & 31, warp = t >> 5;
    for (int o = 16; o; o >>= 1) s += __shfl_down_sync(0xffffffffu, s, o);
    __shared__ int ws[8];
    if (lane == 0) ws[warp] = s;
    __syncthreads();
    if (t == 0) {
        int tot = 0;
        #pragma unroll
        for (int w = 0; w < 8; w++) tot += ws[w];
        g_bsum[blockIdx.x] = tot;
    }
}

__global__ void k_scan3() {
    int t = threadIdx.x, blk = blockIdx.x;   // 256 threads
    __shared__ int ws[8], wo[8], sBoff;
    int lane = t & 31, warp = t >> 5;

    int bv = (t < blk) ? g_bsum[t] : 0;
    for (int o = 16; o; o >>= 1) bv += __shfl_down_sync(0xffffffffu, bv, o);
    if (lane == 0) ws[warp] = bv;
    __syncthreads();
    if (t == 0) {
        int tot = 0;
        #pragma unroll
        for (int w = 0; w < 8; w++) tot += ws[w];
        sBoff = tot;
    }
    __syncthreads();

    int i0 = blk * 512 + t * 2;
    int d0 = (i0 < NN) ? g_deg[i0] : 0;
    int d1 = (i0 + 1 < NN) ? g_deg[i0 + 1] : 0;
    int s = d0 + d1;
    int v = s;
    for (int o = 1; o < 32; o <<= 1) {
        int u = __shfl_up_sync(0xffffffffu, v, o);
        if (lane >= o) v += u;
    }
    if (lane == 31) ws[warp] = v;
    __syncthreads();
    if (t == 0) {
        int run = 0;
        #pragma unroll
        for (int w = 0; w < 8; w++) { wo[w] = run; run += ws[w]; }
    }
    __syncthreads();
    int ex = v - s + wo[warp] + sBoff;
    if (i0 < NN)     { g_start[i0] = ex;          g_cursor[i0] = ex; }
    if (i0 + 1 < NN) { g_start[i0 + 1] = ex + d0; g_cursor[i0 + 1] = ex + d0; }
}

__global__ void k_fill(const int* __restrict__ row, const int* __restrict__ col,
                       const float* __restrict__ ea) {
    int e = blockIdx.x * blockDim.x + threadIdx.x;
    if (e >= EE) return;
    int r = row[e];
    int idx = atomicAdd(&g_cursor[r], 1);
    int2 pk;
    pk.x = col[e];
    pk.y = __float_as_int(ea[e]);
    g_edge[idx] = pk;
}

// hop 0 fused (u==0): warp per node; lanes split edges for third term; emit bf16 u.
__global__ void k_hop0(const float* __restrict__ x,
                       const float* __restrict__ l3w, const float* __restrict__ l3b,
                       const float* __restrict__ l0w, const float* __restrict__ l0b,
                       const float* __restrict__ l1b,
                       const float* __restrict__ l2w, const float* __restrict__ l2b) {
    int warp = threadIdx.x >> 5, lane = threadIdx.x & 31;
    int n = blockIdx.x * 8 + warp;
    if (n >= NN) return;
    float w = l3w[0], b = l3b[0];
    int s = g_start[n], e = g_start[n + 1];
    float acc = 0.f;
    for (int t = s + lane; t < e; t += 32)
        acc += fmaxf(__int_as_float(g_edge[t].y) * w + b, 0.f);
    for (int o = 16; o; o >>= 1) acc += __shfl_xor_sync(0xffffffffu, acc, o);
    float third = (e > s) ? acc / (float)(e - s) : 0.f;
    float xv = x[n];
    int h0 = lane * 4;
    float v0 = xv * l0w[h0]     + third * l2w[h0]     + l0b[h0]     + l1b[h0]     + l2b[h0];
    float v1 = xv * l0w[h0 + 1] + third * l2w[h0 + 1] + l0b[h0 + 1] + l1b[h0 + 1] + l2b[h0 + 1];
    float v2 = xv * l0w[h0 + 2] + third * l2w[h0 + 2] + l0b[h0 + 2] + l1b[h0 + 2] + l2b[h0 + 2];
    float v3 = xv * l0w[h0 + 3] + third * l2w[h0 + 3] + l0b[h0 + 3] + l1b[h0 + 3] + l2b[h0 + 3];
    __nv_bfloat162 lo = __floats2bfloat162_rn(fmaxf(v0, 0.f), fmaxf(v1, 0.f));
    __nv_bfloat162 hi = __floats2bfloat162_rn(fmaxf(v2, 0.f), fmaxf(v3, 0.f));
    uint2 pk;
    pk.x = *reinterpret_cast<unsigned*>(&lo);
    pk.y = *reinterpret_cast<unsigned*>(&hi);
    reinterpret_cast<uint2*>(g_ub)[(size_t)n * 32 + lane] = pk;
}

// edge aggregation: 2 nodes per warp (16 lanes each, uint4 = 8 bf16 per lane).
// Doubles per-warp MLP. Every lane accumulates the FULL third term redundantly
// (no reduction!); lane hl==0 writes it. Packed edge stream; bf16 mean out.
__global__ void k_gather(const float* __restrict__ l3w, const float* __restrict__ l3b) {
    int warp = threadIdx.x >> 5, lane = threadIdx.x & 31;
    int hl = lane & 15;                      // lane within half-warp
    int n = blockIdx.x * 16 + warp * 2 + (lane >> 4);
    if (n >= NN) return;
    const uint4* ub4 = reinterpret_cast<const uint4*>(g_ub);  // 16 uint4 per node row
    float w = l3w[0], b = l3b[0];
    int s = g_start[n], e = g_start[n + 1];
    float a0x = 0.f, a1x = 0.f, a2x = 0.f, a3x = 0.f;
    float a4x = 0.f, a5x = 0.f, a6x = 0.f, a7x = 0.f;
    float tacc = 0.f;
    int t = s;
    for (; t + 3 < e; t += 4) {
        int2 e0 = g_edge[t],     e1 = g_edge[t + 1];
        int2 e2 = g_edge[t + 2], e3 = g_edge[t + 3];
        float c0 = __int_as_float(e0.y), c1 = __int_as_float(e1.y);
        float c2 = __int_as_float(e2.y), c3 = __int_as_float(e3.y);
        uint4 r0 = ub4[(size_t)e0.x * 16 + hl];
        uint4 r1 = ub4[(size_t)e1.x * 16 + hl];
        uint4 r2 = ub4[(size_t)e2.x * 16 + hl];
        uint4 r3 = ub4[(size_t)e3.x * 16 + hl];
        #define ACC8(R, C) { \
            float2 f0 = __bfloat1622float2(*reinterpret_cast<__nv_bfloat162*>(&R.x)); \
            float2 f1 = __bfloat1622float2(*reinterpret_cast<__nv_bfloat162*>(&R.y)); \
            float2 f2 = __bfloat1622float2(*reinterpret_cast<__nv_bfloat162*>(&R.z)); \
            float2 f3 = __bfloat1622float2(*reinterpret_cast<__nv_bfloat162*>(&R.w)); \
            a0x += C * f0.x; a1x += C * f0.y; a2x += C * f1.x; a3x += C * f1.y; \
            a4x += C * f2.x; a5x += C * f2.y; a6x += C * f3.x; a7x += C * f3.y; }
        ACC8(r0, c0) ACC8(r1, c1) ACC8(r2, c2) ACC8(r3, c3)
        tacc += fmaxf(c0 * w + b, 0.f) + fmaxf(c1 * w + b, 0.f)
              + fmaxf(c2 * w + b, 0.f) + fmaxf(c3 * w + b, 0.f);
    }
    for (; t < e; t++) {
        int2 e0 = g_edge[t];
        float c0 = __int_as_float(e0.y);
        uint4 r0 = ub4[(size_t)e0.x * 16 + hl];
        ACC8(r0, c0)
        tacc += fmaxf(c0 * w + b, 0.f);
    }
    #undef ACC8
    float inv = (e > s) ? 1.f / (float)(e - s) : 0.f;
    __nv_bfloat162 b0 = __floats2bfloat162_rn(a0x * inv, a1x * inv);
    __nv_bfloat162 b1 = __floats2bfloat162_rn(a2x * inv, a3x * inv);
    __nv_bfloat162 b2 = __floats2bfloat162_rn(a4x * inv, a5x * inv);
    __nv_bfloat162 b3 = __floats2bfloat162_rn(a6x * inv, a7x * inv);
    uint4 pk;
    pk.x = *reinterpret_cast<unsigned*>(&b0);
    pk.y = *reinterpret_cast<unsigned*>(&b1);
    pk.z = *reinterpret_cast<unsigned*>(&b2);
    pk.w = *reinterpret_cast<unsigned*>(&b3);
    reinterpret_cast<uint4*>(g_meanb)[(size_t)n * 16 + hl] = pk;
    if (hl == 0) g_third[n] = tacc * inv;
}

// bf16 tensor-core GEMM via mma.sync (base sm_103 ISA) + fused hop epilogue.
// CTA = 128 nodes x 128 cols, K=128. 8 warps; warp w owns rows m0=w*16.
// Always emits bf16 u into g_ub (safe: previous consumer ended at kernel boundary).
__global__ __launch_bounds__(256) void k_hmma(
    const float* __restrict__ x,
    const __nv_bfloat16* __restrict__ wtb,   // [128 c][128 k] bf16 row-major
    const float* __restrict__ l0w, const float* __restrict__ l2w,
    const float* __restrict__ b0, const float* __restrict__ b1,
    const float* __restrict__ b2) {
    extern __shared__ char smem[];
    uint32_t sbase = smem_u32(smem);
    int tid = threadIdx.x, lane = tid & 31, w = tid >> 5;
    int n0g = blockIdx.x * 128;

    // stage A (bf16 mean rows, 8 B per lane-step)
    for (int i = tid; i < 128 * 32; i += 256) {
        int row = i >> 5, u2 = i & 31;
        int n = n0g + row;
        uint2 v = (n < NN) ? g_meanb[(size_t)n * 32 + u2] : make_uint2(0u, 0u);
        *reinterpret_cast<uint2*>(smem + SH_A + row * (ASTB * 2) + u2 * 8) = v;
    }
    // stage B^T
    const uint2* wb = reinterpret_cast<const uint2*>(wtb);
    for (int i = tid; i < 128 * 32; i += 256) {
        int row = i >> 5, u2 = i & 31;
        *reinterpret_cast<uint2*>(smem + SH_B + row * (ASTB * 2) + u2 * 8) = wb[row * 32 + u2];
    }
    if (tid < 128) {
        reinterpret_cast<float*>(smem + SH_CB)[tid] = b0[tid] + b1[tid] + b2[tid];
        reinterpret_cast<float*>(smem + SH_C0)[tid] = l0w[tid];
        reinterpret_cast<float*>(smem + SH_C2)[tid] = l2w[tid];
    }
    __syncthreads();

    // ldmatrix lane addressing
    int lg = lane >> 3, li = lane & 7;
    int rowA = w * 16 + (lg & 1) * 8 + li;          // A rows for this warp
    uint32_t aBase = sbase + SH_A + rowA * (ASTB * 2) + ((lg >> 1) * 8) * 2;
    int rowBb = (lg >> 1) * 8 + li;                 // B row base within n-tile pair
    uint32_t bBase = sbase + SH_B + rowBb * (ASTB * 2) + ((lg & 1) * 8) * 2;

    float acc[16][4];
    #pragma unroll
    for (int t = 0; t < 16; t++)
        #pragma unroll
        for (int j = 0; j < 4; j++) acc[t][j] = 0.f;

    #pragma unroll 1
    for (int ks = 0; ks < 8; ks++) {
        uint32_t kb2 = ks * 32;   // kb*2 bytes
        uint32_t a0, a1, a2, a3;
        asm volatile("ldmatrix.sync.aligned.m8n8.x4.shared.b16 {%0,%1,%2,%3}, [%4];"
                     : "=r"(a0), "=r"(a1), "=r"(a2), "=r"(a3) : "r"(aBase + kb2));
        #pragma unroll
        for (int np = 0; np < 8; np++) {
            uint32_t r0, r1, r2, r3;
            asm volatile("ldmatrix.sync.aligned.m8n8.x4.shared.b16 {%0,%1,%2,%3}, [%4];"
                         : "=r"(r0), "=r"(r1), "=r"(r2), "=r"(r3)
                         : "r"(bBase + np * 16 * (ASTB * 2) + kb2));
            asm volatile(
                "mma.sync.aligned.m16n8k16.row.col.f32.bf16.bf16.f32 "
                "{%0,%1,%2,%3}, {%4,%5,%6,%7}, {%8,%9}, {%0,%1,%2,%3};"
                : "+f"(acc[2 * np][0]), "+f"(acc[2 * np][1]),
                  "+f"(acc[2 * np][2]), "+f"(acc[2 * np][3])
                : "r"(a0), "r"(a1), "r"(a2), "r"(a3), "r"(r0), "r"(r1));
            asm volatile(
                "mma.sync.aligned.m16n8k16.row.col.f32.bf16.bf16.f32 "
                "{%0,%1,%2,%3}, {%4,%5,%6,%7}, {%8,%9}, {%0,%1,%2,%3};"
                : "+f"(acc[2 * np + 1][0]), "+f"(acc[2 * np + 1][1]),
                  "+f"(acc[2 * np + 1][2]), "+f"(acc[2 * np + 1][3])
                : "r"(a0), "r"(a1), "r"(a2), "r"(a3), "r"(r2), "r"(r3));
        }
    }

    // epilogue: thread holds rows (m0 + lane/4) and (+8), cols 8t + (lane%4)*2, +1
    int q = lane & 3;
    int row0 = w * 16 + (lane >> 2), row1 = row0 + 8;
    int nA = n0g + row0, nB = n0g + row1;
    float xA = 0.f, tA = 0.f, xB = 0.f, tB = 0.f;
    if (nA < NN) { xA = x[nA]; tA = g_third[nA]; }
    if (nB < NN) { xB = x[nB]; tB = g_third[nB]; }
    const float* sCB = reinterpret_cast<const float*>(smem + SH_CB);
    const float* sC0 = reinterpret_cast<const float*>(smem + SH_C0);
    const float* sC2 = reinterpret_cast<const float*>(smem + SH_C2);

    #pragma unroll
    for (int t = 0; t < 16; t++) {
        int c = t * 8 + q * 2;
        float2 bb = *reinterpret_cast<const float2*>(&sCB[c]);
        float2 w0 = *reinterpret_cast<const float2*>(&sC0[c]);
        float2 w2 = *reinterpret_cast<const float2*>(&sC2[c]);
        float oA0 = fmaxf(xA * w0.x + tA * w2.x + bb.x + acc[t][0], 0.f);
        float oA1 = fmaxf(xA * w0.y + tA * w2.y + bb.y + acc[t][1], 0.f);
        float oB0 = fmaxf(xB * w0.x + tB * w2.x + bb.x + acc[t][2], 0.f);
        float oB1 = fmaxf(xB * w0.y + tB * w2.y + bb.y + acc[t][3], 0.f);
        if (nA < NN) g_ub[(size_t)nA * 64 + (c >> 1)] = __floats2bfloat162_rn(oA0, oA1);
        if (nB < NN) g_ub[(size_t)nB * 64 + (c >> 1)] = __floats2bfloat162_rn(oB0, oB1);
    }
}

// per-graph pooled sums (batch sorted -> register accumulate, flush on change)
// reads bf16 u
__global__ void k_pool(const float* __restrict__ x, const int* __restrict__ batch) {
    int h = threadIdx.x;               // 128
    int n0 = blockIdx.x * 128;
    if (n0 >= NN) return;
    int n1 = n0 + 128; if (n1 > NN) n1 = NN;
    const __nv_bfloat16* ubh = reinterpret_cast<const __nv_bfloat16*>(g_ub);
    int gcur = batch[n0];
    float a0 = 0.f, a1 = 0.f, c0 = 0.f, c1 = 0.f;
    for (int n = n0; n < n1; n++) {
        int g = batch[n];
        if (g != gcur) {
            atomicAdd(&g_gs0[gcur * HH + h], a0);
            atomicAdd(&g_gs1[gcur * HH + h], a1);
            if (h == 0) { atomicAdd(&g_cnt[gcur], c0); atomicAdd(&g_cnt[BB + gcur], c1); }
            a0 = a1 = c0 = c1 = 0.f;
            gcur = g;
        }
        float xv = x[n];
        float uv = __bfloat162float(ubh[(size_t)n * HH + h]);
        a0 += uv * (1.f - xv); a1 += uv * xv;
        c0 += 1.f - xv;        c1 += xv;
    }
    atomicAdd(&g_gs0[gcur * HH + h], a0);
    atomicAdd(&g_gs1[gcur * HH + h], a1);
    if (h == 0) { atomicAdd(&g_cnt[gcur], c0); atomicAdd(&g_cnt[BB + gcur], c1); }
}

// per-graph: hc0/hc1, folded attention vectors v0/v1 = att_w @ hc, and 10 scalars
__global__ void k_graph(const float* __restrict__ attw, const float* __restrict__ attb) {
    __shared__ float hc0[HH], hc1[HH], v0[2 * HH], v1[2 * HH];
    int g = blockIdx.x, t = threadIdx.x;  // 256 threads
    if (t < HH) {
        float c0 = g_cnt[g], c1 = g_cnt[BB + g];
        hc0[t] = (c0 > 0.f) ? g_gs0[g * HH + t] / c0 : 0.f;
        hc1[t] = (c1 > 0.f) ? g_gs1[g * HH + t] / c1 : 0.f;
    }
    __syncthreads();
    {
        float s0 = 0.f, s1 = 0.f;
        const float* wrow = attw + t * HH;
        for (int j = 0; j < HH; j++) { float w = wrow[j]; s0 += w * hc0[j]; s1 += w * hc1[j]; }
        v0[t] = s0; v1[t] = s1;
        if (t < HH) { g_v0t[g * HH + t] = s0; g_v1t[g * HH + t] = s1; }
    }
    __syncthreads();
    int warp = t >> 5, lane = t & 31;
    for (int id = warp; id < 10; id += 8) {
        const float* vec; const float* hc;
        switch (id) {
            case 0: vec = attb;     hc = hc0; break;  // s0
            case 1: vec = attb;     hc = hc1; break;  // s1
            case 2: vec = g_spvec;  hc = hc0; break;  // p0
            case 3: vec = g_spvec;  hc = hc1; break;  // p1
            case 4: vec = g_acbot;  hc = hc0; break;  // a0
            case 5: vec = g_acbot;  hc = hc1; break;  // a1
            case 6: vec = v0 + HH;  hc = hc0; break;  // d00
            case 7: vec = v0 + HH;  hc = hc1; break;  // d01
            case 8: vec = v1 + HH;  hc = hc0; break;  // d10
            default: vec = v1 + HH; hc = hc1; break;  // d11
        }
        float s = 0.f;
        for (int j = lane; j < HH; j += 32) s += vec[j] * hc[j];
        for (int o = 16; o; o >>= 1) s += __shfl_down_sync(0xffffffffu, s, o);
        if (lane == 0) g_scal[g * 10 + id] = s;
    }
}

// per-node head: 3 dots of length 128 + softmax over 2 + folded output (bf16 u)
__global__ void k_final(const float* __restrict__ x, const int* __restrict__ batch,
                        float* __restrict__ out) {
    int warp = threadIdx.x >> 5, lane = threadIdx.x & 31;
    int n = blockIdx.x * 8 + warp;
    if (n >= NN) return;
    int g = batch[n];
    uint2 upk = reinterpret_cast<const uint2*>(g_ub)[(size_t)n * 32 + lane];
    float2 ulo = __bfloat1622float2(*reinterpret_cast<__nv_bfloat162*>(&upk.x));
    float2 uhi = __bfloat1622float2(*reinterpret_cast<__nv_bfloat162*>(&upk.y));
    float4 uv = make_float4(ulo.x, ulo.y, uhi.x, uhi.y);
    float4 vA = *reinterpret_cast<const float4*>(&g_v0t[g * HH + lane * 4]);
    float4 vB = *reinterpret_cast<const float4*>(&g_v1t[g * HH + lane * 4]);
    float4 vC = *reinterpret_cast<const float4*>(&g_actop[lane * 4]);
    float da = uv.x * vA.x + uv.y * vA.y + uv.z * vA.z + uv.w * vA.w;
    float db = uv.x * vB.x + uv.y * vB.y + uv.z * vB.z + uv.w * vB.w;
    float dc = uv.x * vC.x + uv.y * vC.y + uv.z * vC.z + uv.w * vC.w;
    for (int o = 16; o; o >>= 1) {
        da += __shfl_down_sync(0xffffffffu, da, o);
        db += __shfl_down_sync(0xffffffffu, db, o);
        dc += __shfl_down_sync(0xffffffffu, dc, o);
    }
    if (lane == 0) {
        const float* sc = &g_scal[g * 10];
        bool xb = x[n] > 0.5f;
        float w0 = da + (xb ? sc[6] : sc[7]) + sc[0];
        float w1 = db + (xb ? sc[8] : sc[9]) + sc[1];
        float m = fmaxf(w0, w1);
        float e0 = __expf(w0 - m), e1 = __expf(w1 - m);
        float sw = e0 / (e0 + e1);
        out[n] = sw * sc[2] + (1.f - sw) * sc[3] + dc + (xb ? sc[4] : sc[5]) + g_c0;
    }
}

// ---------------- launch ----------------
extern "C" void kernel_launch(void* const* d_in, const int* in_sizes, int n_in,
                              void* d_out, int out_size) {
    int base = (n_in >= 21) ? 5 : 4;
    const float* x     = (const float*)d_in[0];
    const int*   ei    = (const int*)d_in[1];
    const float* ea    = (const float*)d_in[2];
    const int*   batch = (const int*)d_in[3];
    const float* l0w   = (const float*)d_in[base + 0];
    const float* l0b   = (const float*)d_in[base + 1];
    const float* l1w   = (const float*)d_in[base + 2];
    const float* l1b   = (const float*)d_in[base + 3];
    const float* l2w   = (const float*)d_in[base + 4];
    const float* l2b   = (const float*)d_in[base + 5];
    const float* l3w   = (const float*)d_in[base + 6];
    const float* l3b   = (const float*)d_in[base + 7];
    const float* attw  = (const float*)d_in[base + 8];
    const float* attb  = (const float*)d_in[base + 9];
    const float* spw   = (const float*)d_in[base + 10];
    const float* spb   = (const float*)d_in[base + 11];
    const float* acw   = (const float*)d_in[base + 12];
    const float* acb   = (const float*)d_in[base + 13];
    const float* lastw = (const float*)d_in[base + 14];
    const float* lastb = (const float*)d_in[base + 15];
    const int* row = ei;
    const int* col = ei + EE;
    float* out = (float*)d_out;

    static __nv_bfloat16* wtb_dev = nullptr;
    if (!wtb_dev) cudaGetSymbolAddress((void**)&wtb_dev, g_wtb);

    cudaFuncSetAttribute(k_hmma, cudaFuncAttributeMaxDynamicSharedMemorySize, SH_TOTAL);

    k_zero<<<(NN + 255) / 256, 256>>>(spw, spb, acw, acb, lastw, lastb, l1w);
    k_hist<<<(EE + 255) / 256, 256>>>(row);
    k_scan1<<<NB1, 256>>>();
    k_scan3<<<NB1, 256>>>();
    k_fill<<<(EE + 255) / 256, 256>>>(row, col, ea);

    // hop 0 (u == 0): fused third+update, bf16 out
    k_hop0<<<(NN + 7) / 8, 256>>>(x, l3w, l3b, l0w, l0b, l1b, l2w, l2b);

    // hops 1, 2: gather then tensor-core GEMM (bf16 u out)
    for (int i = 1; i < 3; i++) {
        k_gather<<<(NN + 15) / 16, 256>>>(l3w + i, l3b + i);
        k_hmma<<<(NN + 127) / 128, 256, SH_TOTAL>>>(
            x, wtb_dev + (i - 1) * HH * HH,
            l0w + i * HH, l2w + i * HH,
            l0b + i * HH, l1b + i * HH, l2b + i * HH);
    }

    k_pool<<<(NN + 127) / 128, 128>>>(x, batch);
    k_graph<<<BB, 256>>>(attw, attb);
    k_final<<<NN / 8, 256>>>(x, batch, out);
}